// round 1
// baseline (speedup 1.0000x reference)
#include <cuda_runtime.h>
#include <math.h>

#define L      1024
#define DM     768
#define DI     1536
#define NH     12
#define HD     128
#define DS     64
#define NPROJ  4620
#define OFF_X  1536
#define OFF_B  3072
#define OFF_C  3840
#define OFF_DT 4608

// ---------------- scratch (device globals; no allocations allowed) -------------
__device__ float g_proj [L * NPROJ];   // 18.9 MB  projection output
__device__ float g_xconv[L * DI];      // conv+silu(x_ssm)
__device__ float g_dt   [NH * L];      // softplus(dt_raw)+bias   (head-major)
__device__ float g_eneg [NH * L];      // exp(min(-Phi,80))
__device__ float g_ephi [NH * L];      // exp(Phi)
__device__ float g_yssm [L * DI];      // SSM output y
__device__ float g_ybar [L * DI];      // rms-normed, gated y

// ---------------- generic fp32 GEMM:  C[M,N] = A[M,K] * B[N,K]^T ---------------
// Both A and B row-major, K-contiguous (inner-product form).
// Requires: M % BM == 0, K % BK == 0, BM == BN, BM*BK == NT*4.
template<int BM, int BN, int BK, int TM, int TN>
__global__ __launch_bounds__((BM/TM)*(BN/TN))
void sgemm_nt(int M, int N, int K,
              const float* __restrict__ A,
              const float* __restrict__ B,
              float* __restrict__ C)
{
    constexpr int NT = (BM/TM)*(BN/TN);
    static_assert(BM == BN, "square tiles only");
    static_assert(BM*BK == NT*4, "one float4 per thread per tile");

    __shared__ float As[BK][BM];
    __shared__ float Bs[BK][BN];

    const int tid = threadIdx.x;
    const int n0  = blockIdx.x * BN;
    const int m0  = blockIdx.y * BM;
    const int tx  = tid % (BN/TN);
    const int ty  = tid / (BN/TN);

    const int la   = tid * 4;
    const int lrow = la / BK;
    const int lcol = la % BK;

    float acc[TM][TN];
#pragma unroll
    for (int i = 0; i < TM; i++)
#pragma unroll
        for (int j = 0; j < TN; j++) acc[i][j] = 0.f;

    for (int k0 = 0; k0 < K; k0 += BK) {
        // A tile (m rows always in range: M multiple of BM)
        float4 av = *(const float4*)&A[(size_t)(m0 + lrow) * K + k0 + lcol];
        As[lcol+0][lrow] = av.x;  As[lcol+1][lrow] = av.y;
        As[lcol+2][lrow] = av.z;  As[lcol+3][lrow] = av.w;
        // B tile (guard N edge)
        float4 bv = make_float4(0.f, 0.f, 0.f, 0.f);
        if (n0 + lrow < N)
            bv = *(const float4*)&B[(size_t)(n0 + lrow) * K + k0 + lcol];
        Bs[lcol+0][lrow] = bv.x;  Bs[lcol+1][lrow] = bv.y;
        Bs[lcol+2][lrow] = bv.z;  Bs[lcol+3][lrow] = bv.w;

        __syncthreads();
#pragma unroll
        for (int k = 0; k < BK; k++) {
            float ra[TM], rb[TN];
#pragma unroll
            for (int i = 0; i < TM; i++) ra[i] = As[k][ty*TM + i];
#pragma unroll
            for (int j = 0; j < TN; j++) rb[j] = Bs[k][tx*TN + j];
#pragma unroll
            for (int i = 0; i < TM; i++)
#pragma unroll
                for (int j = 0; j < TN; j++)
                    acc[i][j] = fmaf(ra[i], rb[j], acc[i][j]);
        }
        __syncthreads();
    }

#pragma unroll
    for (int i = 0; i < TM; i++) {
        const int m = m0 + ty*TM + i;
#pragma unroll
        for (int j = 0; j < TN; j++) {
            const int n = n0 + tx*TN + j;
            if (n < N) C[(size_t)m * N + n] = acc[i][j];
        }
    }
}

// ---------------- conv1d(window 4, causal) + silu on x_ssm ---------------------
__global__ void conv_silu_kernel(const float* __restrict__ conv_w,
                                 const float* __restrict__ conv_b)
{
    int id = blockIdx.x * blockDim.x + threadIdx.x;
    if (id >= L * DI) return;
    int t = id / DI, c = id % DI;
    float acc = conv_b[c];
#pragma unroll
    for (int i = 0; i < 4; i++) {
        int ts = t + i - 3;
        if (ts >= 0)
            acc = fmaf(g_proj[(size_t)ts * NPROJ + OFF_X + c], conv_w[c*4 + i], acc);
    }
    float sig = 1.f / (1.f + expf(-acc));
    g_xconv[id] = acc * sig;
}

// ---------------- dt = softplus(dt_raw)+bias; Phi = cumsum(A*dt) per head ------
// One warp per head; chunked warp-inclusive scan.
__global__ void dt_phi_kernel(const float* __restrict__ A_log,
                              const float* __restrict__ dt_bias)
{
    const int h = blockIdx.x;
    const int l = threadIdx.x;       // 0..31
    const float Ah   = -expf(A_log[h]);
    const float bias = dt_bias[h];
    float carry = 0.f;
    for (int c = 0; c < L/32; c++) {
        int t = c*32 + l;
        float xr = g_proj[(size_t)t * NPROJ + OFF_DT + h];
        // jax.nn.softplus(x) = max(x,0) + log1p(exp(-|x|))
        float dt = fmaxf(xr, 0.f) + log1pf(expf(-fabsf(xr))) + bias;
        g_dt[h*L + t] = dt;
        float s = Ah * dt;
#pragma unroll
        for (int o = 1; o < 32; o <<= 1) {
            float v = __shfl_up_sync(0xffffffffu, s, o);
            if (l >= o) s += v;
        }
        float Phi = carry + s;
        g_eneg[h*L + t] = expf(fminf(-Phi, 80.f));
        g_ephi[h*L + t] = expf(Phi);        // underflows to 0 like the reference
        carry = __shfl_sync(0xffffffffu, Phi, 31);
    }
}

// ---------------- SSM scan replicating reference cumsum numerics ---------------
// grid(NH, 16): head h, i-group of 8 head-dims. 8 warps: warp w owns i = ig*8+w.
// Lane l owns states (i, j=l) and (i, j=l+32). acc replicates the cumsum;
// h_t = exp(Phi_t) * acc ; y_t = sum_j C_j h_j + Dp*x_i (warp shfl reduce).
#define TC 64
__global__ __launch_bounds__(256)
void ssm_scan_kernel(const float* __restrict__ Dp)
{
    const int h  = blockIdx.x;
    const int ig = blockIdx.y;
    const int w  = threadIdx.x >> 5;
    const int l  = threadIdx.x & 31;

    __shared__ float Bsh[TC][DS];
    __shared__ float Csh[TC][DS];
    __shared__ float xsh[TC][8];
    __shared__ float sdt[TC], sen[TC], sep[TC];

    float acc0 = 0.f, acc1 = 0.f;
    const float dph  = Dp[h];
    const int ibase  = h * HD + ig * 8;

    for (int t0 = 0; t0 < L; t0 += TC) {
        __syncthreads();
        for (int idx = threadIdx.x; idx < TC*DS; idx += 256) {
            int tt = idx / DS, j = idx % DS;
            size_t row = (size_t)(t0 + tt) * NPROJ;
            Bsh[tt][j] = g_proj[row + OFF_B + h*DS + j];
            Csh[tt][j] = g_proj[row + OFF_C + h*DS + j];
        }
        for (int idx = threadIdx.x; idx < TC*8; idx += 256) {
            int tt = idx / 8, ii = idx % 8;
            xsh[tt][ii] = g_xconv[(size_t)(t0 + tt) * DI + ibase + ii];
        }
        if (threadIdx.x < TC) {
            sdt[threadIdx.x] = g_dt  [h*L + t0 + threadIdx.x];
            sen[threadIdx.x] = g_eneg[h*L + t0 + threadIdx.x];
            sep[threadIdx.x] = g_ephi[h*L + t0 + threadIdx.x];
        }
        __syncthreads();

        for (int tt = 0; tt < TC; tt++) {
            float e   = sen[tt];
            float p   = sep[tt];
            float dtt = sdt[tt];
            float xi  = xsh[tt][w];
            float db0 = dtt * Bsh[tt][l];
            float db1 = dtt * Bsh[tt][l + 32];
            acc0 = fmaf(e, db0 * xi, acc0);     // e * (dB * x)  -- reference order
            acc1 = fmaf(e, db1 * xi, acc1);
            float part = Csh[tt][l]      * (p * acc0)
                       + Csh[tt][l + 32] * (p * acc1);
#pragma unroll
            for (int o = 16; o > 0; o >>= 1)
                part += __shfl_xor_sync(0xffffffffu, part, o);
            if (l == 0)
                g_yssm[(size_t)(t0 + tt) * DI + ibase + w] = part + dph * xi;
        }
    }
}

// ---------------- RMS norm over DI + silu(z) gate ------------------------------
__global__ void rms_gate_kernel(const float* __restrict__ norm_w)
{
    const int t = blockIdx.x;
    __shared__ float red[256];
    float s = 0.f;
    for (int c = threadIdx.x; c < DI; c += 256) {
        float v = g_yssm[(size_t)t * DI + c];
        s = fmaf(v, v, s);
    }
    red[threadIdx.x] = s;
    __syncthreads();
    for (int o = 128; o > 0; o >>= 1) {
        if (threadIdx.x < o) red[threadIdx.x] += red[threadIdx.x + o];
        __syncthreads();
    }
    float rms = rsqrtf(red[0] / (float)DI + 1e-5f);
    for (int c = threadIdx.x; c < DI; c += 256) {
        float v = g_yssm[(size_t)t * DI + c];
        float z = g_proj[(size_t)t * NPROJ + c];
        float sig = 1.f / (1.f + expf(-z));
        g_ybar[(size_t)t * DI + c] = v * rms * norm_w[c] * (z * sig);
    }
}

// ---------------- launch --------------------------------------------------------
extern "C" void kernel_launch(void* const* d_in, const int* in_sizes, int n_in,
                              void* d_out, int out_size)
{
    const float* x       = (const float*)d_in[0];
    const float* W_in    = (const float*)d_in[1];
    const float* conv_w  = (const float*)d_in[2];
    const float* conv_b  = (const float*)d_in[3];
    const float* A_log   = (const float*)d_in[4];
    const float* Dp      = (const float*)d_in[5];
    const float* dt_bias = (const float*)d_in[6];
    const float* W_out   = (const float*)d_in[7];
    const float* norm_w  = (const float*)d_in[8];
    float* out = (float*)d_out;

    float *proj_p, *ybar_p;
    cudaGetSymbolAddress((void**)&proj_p, g_proj);
    cudaGetSymbolAddress((void**)&ybar_p, g_ybar);

    // 1) proj = x @ W_in^T      (1024 x 4620 x 768)
    sgemm_nt<128,128,8,8,8><<<dim3((NPROJ + 127)/128, L/128), 256>>>(
        L, NPROJ, DM, x, W_in, proj_p);

    // 2) causal conv1d + silu on x_ssm slice
    conv_silu_kernel<<<(L*DI + 255)/256, 256>>>(conv_w, conv_b);

    // 3) dt / Phi / exp tables (one warp per head)
    dt_phi_kernel<<<NH, 32>>>(A_log, dt_bias);

    // 4) SSM scan (reference cumsum numerics)
    ssm_scan_kernel<<<dim3(NH, 16), 256>>>(Dp);

    // 5) RMS norm + silu(z) gate
    rms_gate_kernel<<<L, 256>>>(norm_w);

    // 6) out = ybar @ W_out^T   (1024 x 768 x 1536)
    sgemm_nt<64,64,16,4,4><<<dim3(DM/64, L/64), 256>>>(
        L, DM, DI, ybar_p, W_out, out);
}

// round 3
// speedup vs baseline: 1.2698x; 1.2698x over previous
#include <cuda_runtime.h>
#include <math.h>

#define L      1024
#define DM     768
#define DI     1536
#define NH     12
#define HD     128
#define DS     64
#define NPROJ  4620
#define OFF_X  1536
#define OFF_B  3072
#define OFF_C  3840
#define OFF_DT 4608
#define NC     16         // chunks
#define CT     64         // chunk length
#define DSP    (DS + 4)   // padded smem row stride (16B-aligned)

// ---------------- scratch (device globals) -------------------------------------
__device__ float g_proj [L * NPROJ];
__device__ float g_xconv[L * DI];
__device__ float g_dt   [NH * L];
__device__ float g_eneg [NH * L];
__device__ float g_ephi [NH * L];
__device__ float g_yssm [L * DI];
__device__ float g_ybar [L * DI];
__device__ float g_dS   [NH * NC * DS * HD];   // per-chunk state increments
__device__ float g_S    [NH * NC * DS * HD];   // exclusive-prefix states

// ---------------- fp32 GEMM:  C[M,N] = A[M,K]*B[N,K]^T, double-buffered --------
template<int BM, int BN, int BK, int TM, int TN>
__global__ __launch_bounds__((BM/TM)*(BN/TN))
void sgemm_nt(int M, int N, int K,
              const float* __restrict__ A,
              const float* __restrict__ B,
              float* __restrict__ C)
{
    constexpr int NT = (BM/TM)*(BN/TN);
    static_assert(BM == BN, "square tiles only");
    static_assert(BM*BK == NT*4, "one float4 per thread per tile");

    __shared__ float As[BK][BM];
    __shared__ float Bs[BK][BN];

    const int tid = threadIdx.x;
    const int n0  = blockIdx.x * BN;
    const int m0  = blockIdx.y * BM;
    const int tx  = tid % (BN/TN);
    const int ty  = tid / (BN/TN);

    const int la   = tid * 4;
    const int lrow = la / BK;
    const int lcol = la % BK;

    float acc[TM][TN];
#pragma unroll
    for (int i = 0; i < TM; i++)
#pragma unroll
        for (int j = 0; j < TN; j++) acc[i][j] = 0.f;

    // first tile
    float4 av = *(const float4*)&A[(size_t)(m0 + lrow) * K + lcol];
    float4 bv = make_float4(0.f,0.f,0.f,0.f);
    if (n0 + lrow < N)
        bv = *(const float4*)&B[(size_t)(n0 + lrow) * K + lcol];
    As[lcol+0][lrow]=av.x; As[lcol+1][lrow]=av.y; As[lcol+2][lrow]=av.z; As[lcol+3][lrow]=av.w;
    Bs[lcol+0][lrow]=bv.x; Bs[lcol+1][lrow]=bv.y; Bs[lcol+2][lrow]=bv.z; Bs[lcol+3][lrow]=bv.w;
    __syncthreads();

    for (int k0 = 0; k0 < K; k0 += BK) {
        const bool more = (k0 + BK < K);
        float4 av2, bv2;
        if (more) {
            av2 = *(const float4*)&A[(size_t)(m0 + lrow) * K + k0 + BK + lcol];
            bv2 = make_float4(0.f,0.f,0.f,0.f);
            if (n0 + lrow < N)
                bv2 = *(const float4*)&B[(size_t)(n0 + lrow) * K + k0 + BK + lcol];
        }
#pragma unroll
        for (int k = 0; k < BK; k++) {
            float ra[TM], rb[TN];
#pragma unroll
            for (int i = 0; i < TM; i += 4)
                *(float4*)&ra[i] = *(const float4*)&As[k][ty*TM + i];
#pragma unroll
            for (int j = 0; j < TN; j += 4)
                *(float4*)&rb[j] = *(const float4*)&Bs[k][tx*TN + j];
#pragma unroll
            for (int i = 0; i < TM; i++)
#pragma unroll
                for (int j = 0; j < TN; j++)
                    acc[i][j] = fmaf(ra[i], rb[j], acc[i][j]);
        }
        if (more) {
            __syncthreads();
            As[lcol+0][lrow]=av2.x; As[lcol+1][lrow]=av2.y; As[lcol+2][lrow]=av2.z; As[lcol+3][lrow]=av2.w;
            Bs[lcol+0][lrow]=bv2.x; Bs[lcol+1][lrow]=bv2.y; Bs[lcol+2][lrow]=bv2.z; Bs[lcol+3][lrow]=bv2.w;
            __syncthreads();
        }
    }

#pragma unroll
    for (int i = 0; i < TM; i++) {
        const int m = m0 + ty*TM + i;
#pragma unroll
        for (int j = 0; j < TN; j++) {
            const int n = n0 + tx*TN + j;
            if (n < N) C[(size_t)m * N + n] = acc[i][j];
        }
    }
}

// ---------------- conv1d(4, causal) + silu -------------------------------------
__global__ void conv_silu_kernel(const float* __restrict__ conv_w,
                                 const float* __restrict__ conv_b)
{
    int id = blockIdx.x * blockDim.x + threadIdx.x;
    if (id >= L * DI) return;
    int t = id / DI, c = id % DI;
    float acc = conv_b[c];
#pragma unroll
    for (int i = 0; i < 4; i++) {
        int ts = t + i - 3;
        if (ts >= 0)
            acc = fmaf(g_proj[(size_t)ts * NPROJ + OFF_X + c], conv_w[c*4 + i], acc);
    }
    float sig = 1.f / (1.f + expf(-acc));
    g_xconv[id] = acc * sig;
}

// ---------------- dt / Phi / exp tables ----------------------------------------
__global__ void dt_phi_kernel(const float* __restrict__ A_log,
                              const float* __restrict__ dt_bias)
{
    const int h = blockIdx.x;
    const int l = threadIdx.x;
    const float Ah   = -expf(A_log[h]);
    const float bias = dt_bias[h];
    float carry = 0.f;
    for (int c = 0; c < L/32; c++) {
        int t = c*32 + l;
        float xr = g_proj[(size_t)t * NPROJ + OFF_DT + h];
        float dt = fmaxf(xr, 0.f) + log1pf(expf(-fabsf(xr))) + bias;
        g_dt[h*L + t] = dt;
        float s = Ah * dt;
#pragma unroll
        for (int o = 1; o < 32; o <<= 1) {
            float v = __shfl_up_sync(0xffffffffu, s, o);
            if (l >= o) s += v;
        }
        float Phi = carry + s;
        g_eneg[h*L + t] = expf(fminf(-Phi, 80.f));
        g_ephi[h*L + t] = expf(Phi);
        carry = __shfl_sync(0xffffffffu, Phi, 31);
    }
}

// ---------------- SSD stage A: per-chunk state increment -----------------------
// dS[h,c][j][i] = sum_{u in chunk} B[u][j] * (eneg_u*dt_u*x[u][i])
__global__ __launch_bounds__(256)
void chunk_dstate_kernel()
{
    const int h = blockIdx.x;
    const int c = blockIdx.y;
    const int t0 = c * CT;

    __shared__ float Bsh[CT][DS];        // stride 64 floats: 16B-aligned
    __shared__ float Xsh[CT][HD];        // stride 128 floats: 16B-aligned

    const int tid = threadIdx.x;
    for (int idx = tid*4; idx < CT*DS; idx += 256*4) {
        int u = idx / DS, j = idx % DS;
        *(float4*)&Bsh[u][j] =
            *(const float4*)&g_proj[(size_t)(t0+u)*NPROJ + OFF_B + h*DS + j];
    }
    for (int idx = tid*4; idx < CT*HD; idx += 256*4) {
        int u = idx / HD, i = idx % HD;
        float su = g_eneg[h*L + t0 + u] * g_dt[h*L + t0 + u];
        float4 xv = *(const float4*)&g_xconv[(size_t)(t0+u)*DI + h*HD + i];
        xv.x *= su; xv.y *= su; xv.z *= su; xv.w *= su;
        *(float4*)&Xsh[u][i] = xv;
    }
    __syncthreads();

    const int lane = tid & 31;
    const int ty   = tid >> 5;          // 0..7
    const int j0   = ty * 8;
    const int i0   = lane * 4;

    float acc[8][4];
#pragma unroll
    for (int a = 0; a < 8; a++)
#pragma unroll
        for (int b = 0; b < 4; b++) acc[a][b] = 0.f;

    for (int u = 0; u < CT; u++) {
        float4 xv = *(const float4*)&Xsh[u][i0];
#pragma unroll
        for (int a = 0; a < 8; a++) {
            float bj = Bsh[u][j0 + a];
            acc[a][0] = fmaf(bj, xv.x, acc[a][0]);
            acc[a][1] = fmaf(bj, xv.y, acc[a][1]);
            acc[a][2] = fmaf(bj, xv.z, acc[a][2]);
            acc[a][3] = fmaf(bj, xv.w, acc[a][3]);
        }
    }
    float* dst = &g_dS[((size_t)(h*NC + c)) * DS * HD];
#pragma unroll
    for (int a = 0; a < 8; a++)
        *(float4*)&dst[(j0+a)*HD + i0] = *(float4*)&acc[a][0];
}

// ---------------- SSD stage B: exclusive prefix over chunks --------------------
__global__ void state_prefix_kernel()
{
    int g = blockIdx.x * blockDim.x + threadIdx.x;   // over NH*DS*HD
    if (g >= NH * DS * HD) return;
    int h = g / (DS*HD);
    int e = g % (DS*HD);
    float run = 0.f;
    for (int c = 0; c < NC; c++) {
        size_t idx = ((size_t)(h*NC + c)) * DS * HD + e;
        g_S[idx] = run;
        run += g_dS[idx];
    }
}

// ---------------- SSD stage C: per-chunk output --------------------------------
// y[t][i] = sum_{u<=t} G[t][u]*x[u][i] + ephi_t * sum_j C[t][j]*S[j][i] + Dp*x[t][i]
// G[t][u] = ephi_t * eneg_u * dt_u * (C_t . B_u)
__global__ __launch_bounds__(256)
void ssd_output_kernel(const float* __restrict__ Dp)
{
    const int h = blockIdx.x;
    const int c = blockIdx.y;
    const int t0 = c * CT;

    __shared__ float Csh [CT][DSP];      // padded stride 68 floats (16B-aligned)
    __shared__ float BGsh[CT][DSP];      // B, then overwritten with G
    __shared__ float sphi[CT], scoef[CT];

    const int tid = threadIdx.x;
    for (int idx = tid*4; idx < CT*DS; idx += 256*4) {
        int u = idx / DS, j = idx % DS;
        size_t row = (size_t)(t0+u) * NPROJ;
        *(float4*)&Csh [u][j] = *(const float4*)&g_proj[row + OFF_C + h*DS + j];
        *(float4*)&BGsh[u][j] = *(const float4*)&g_proj[row + OFF_B + h*DS + j];
    }
    if (tid < CT) {
        sphi [tid] = g_ephi[h*L + t0 + tid];
        scoef[tid] = g_eneg[h*L + t0 + tid] * g_dt[h*L + t0 + tid];
    }
    __syncthreads();

    // ---- stage 1: G = mask( (C B^T) * sphi_t * scoef_u ) -----------------
    {
        const int ut = tid & 15;
        const int tt = tid >> 4;
        const int ta = tt * 4;
        const int ua = ut * 4;
        float g[4][4];
#pragma unroll
        for (int a = 0; a < 4; a++)
#pragma unroll
            for (int b = 0; b < 4; b++) g[a][b] = 0.f;
        for (int k = 0; k < DS; k++) {
            float cr[4], br[4];
#pragma unroll
            for (int a = 0; a < 4; a++) cr[a] = Csh [ta+a][k];
#pragma unroll
            for (int b = 0; b < 4; b++) br[b] = BGsh[ua+b][k];
#pragma unroll
            for (int a = 0; a < 4; a++)
#pragma unroll
                for (int b = 0; b < 4; b++)
                    g[a][b] = fmaf(cr[a], br[b], g[a][b]);
        }
        __syncthreads();   // everyone done reading B
#pragma unroll
        for (int a = 0; a < 4; a++)
#pragma unroll
            for (int b = 0; b < 4; b++) {
                int t = ta + a, u = ua + b;
                float m = (t >= u) ? sphi[t] * scoef[u] : 0.f;
                BGsh[t][u] = m * g[a][b];
            }
        __syncthreads();
    }

    // ---- stages 2+3: Y = G*X + sphi * (C*S) + Dp*X -----------------------
    const int lane = tid & 31;
    const int tg   = tid >> 5;           // 0..7
    const int tb   = tg * 8;             // 8 t's per thread
    const int i0   = lane * 4;
    const int hbase = h * HD;
    const float dph = Dp[h];
    const float* Srow = &g_S[((size_t)(h*NC + c)) * DS * HD];

    float accI[8][4], accS[8][4];
#pragma unroll
    for (int s = 0; s < 8; s++)
#pragma unroll
        for (int b = 0; b < 4; b++) { accI[s][b] = 0.f; accS[s][b] = 0.f; }

    for (int u = 0; u < CT; u++) {
        float4 xv = *(const float4*)&g_xconv[(size_t)(t0+u)*DI + hbase + i0];
#pragma unroll
        for (int s = 0; s < 8; s++) {
            float gv = BGsh[tb+s][u];
            accI[s][0] = fmaf(gv, xv.x, accI[s][0]);
            accI[s][1] = fmaf(gv, xv.y, accI[s][1]);
            accI[s][2] = fmaf(gv, xv.z, accI[s][2]);
            accI[s][3] = fmaf(gv, xv.w, accI[s][3]);
        }
    }
    for (int j = 0; j < DS; j++) {
        float4 sv = *(const float4*)&Srow[j*HD + i0];
#pragma unroll
        for (int s = 0; s < 8; s++) {
            float cj = Csh[tb+s][j];
            accS[s][0] = fmaf(cj, sv.x, accS[s][0]);
            accS[s][1] = fmaf(cj, sv.y, accS[s][1]);
            accS[s][2] = fmaf(cj, sv.z, accS[s][2]);
            accS[s][3] = fmaf(cj, sv.w, accS[s][3]);
        }
    }
#pragma unroll
    for (int s = 0; s < 8; s++) {
        int t = tb + s;
        float p = sphi[t];
        float4 xv = *(const float4*)&g_xconv[(size_t)(t0+t)*DI + hbase + i0];
        float4 y;
        y.x = fmaf(p, accS[s][0], accI[s][0]) + dph * xv.x;
        y.y = fmaf(p, accS[s][1], accI[s][1]) + dph * xv.y;
        y.z = fmaf(p, accS[s][2], accI[s][2]) + dph * xv.z;
        y.w = fmaf(p, accS[s][3], accI[s][3]) + dph * xv.w;
        *(float4*)&g_yssm[(size_t)(t0+t)*DI + hbase + i0] = y;
    }
}

// ---------------- RMS norm + silu(z) gate --------------------------------------
__global__ void rms_gate_kernel(const float* __restrict__ norm_w)
{
    const int t = blockIdx.x;
    __shared__ float red[256];
    float s = 0.f;
    for (int c = threadIdx.x; c < DI; c += 256) {
        float v = g_yssm[(size_t)t * DI + c];
        s = fmaf(v, v, s);
    }
    red[threadIdx.x] = s;
    __syncthreads();
    for (int o = 128; o > 0; o >>= 1) {
        if (threadIdx.x < o) red[threadIdx.x] += red[threadIdx.x + o];
        __syncthreads();
    }
    float rms = rsqrtf(red[0] / (float)DI + 1e-5f);
    for (int c = threadIdx.x; c < DI; c += 256) {
        float v = g_yssm[(size_t)t * DI + c];
        float z = g_proj[(size_t)t * NPROJ + c];
        float sig = 1.f / (1.f + expf(-z));
        g_ybar[(size_t)t * DI + c] = v * rms * norm_w[c] * (z * sig);
    }
}

// ---------------- launch --------------------------------------------------------
extern "C" void kernel_launch(void* const* d_in, const int* in_sizes, int n_in,
                              void* d_out, int out_size)
{
    const float* x       = (const float*)d_in[0];
    const float* W_in    = (const float*)d_in[1];
    const float* conv_w  = (const float*)d_in[2];
    const float* conv_b  = (const float*)d_in[3];
    const float* A_log   = (const float*)d_in[4];
    const float* Dp      = (const float*)d_in[5];
    const float* dt_bias = (const float*)d_in[6];
    const float* W_out   = (const float*)d_in[7];
    const float* norm_w  = (const float*)d_in[8];
    float* out = (float*)d_out;

    float *proj_p, *ybar_p;
    cudaGetSymbolAddress((void**)&proj_p, g_proj);
    cudaGetSymbolAddress((void**)&ybar_p, g_ybar);

    // 1) proj = x @ W_in^T      (1024 x 4620 x 768)
    sgemm_nt<128,128,8,8,8><<<dim3((NPROJ + 127)/128, L/128), 256>>>(
        L, NPROJ, DM, x, W_in, proj_p);

    // 2) causal conv1d + silu
    conv_silu_kernel<<<(L*DI + 255)/256, 256>>>(conv_w, conv_b);

    // 3) dt / Phi / exp tables
    dt_phi_kernel<<<NH, 32>>>(A_log, dt_bias);

    // 4a) per-chunk state increments
    chunk_dstate_kernel<<<dim3(NH, NC), 256>>>();

    // 4b) exclusive chunk-state prefix
    state_prefix_kernel<<<(NH*DS*HD + 255)/256, 256>>>();

    // 4c) chunk outputs
    ssd_output_kernel<<<dim3(NH, NC), 256>>>(Dp);

    // 5) RMS norm + gate
    rms_gate_kernel<<<L, 256>>>(norm_w);

    // 6) out = ybar @ W_out^T   (1024 x 768 x 1536)
    sgemm_nt<64,64,16,4,4><<<dim3(DM/64, L/64), 256>>>(
        L, DM, DI, ybar_p, W_out, out);
}

// round 4
// speedup vs baseline: 1.4213x; 1.1193x over previous
#include <cuda_runtime.h>
#include <math.h>
#include <stdint.h>

#define L      1024
#define DM     768
#define DI     1536
#define NH     12
#define HD     128
#define DS     64
#define NPROJ  4620
#define OFF_X  1536
#define OFF_B  3072
#define OFF_C  3840
#define OFF_DT 4608
#define NC     16
#define CT     64
#define DSP    (DS + 4)

// ---------------- scratch -------------------------------------------------------
__device__ float g_proj [L * NPROJ];
__device__ float g_xconv[L * DI];
__device__ float g_dt   [NH * L];
__device__ float g_eneg [NH * L];
__device__ float g_ephi [NH * L];
__device__ float g_yssm [L * DI];
__device__ float g_ybar [L * DI];
__device__ float g_dS   [NH * NC * DS * HD];
__device__ float g_S    [NH * NC * DS * HD];

// ---------------- 3xTF32 tensor-core GEMM: C[M,N] = A[M,K]*B[N,K]^T -------------
__device__ __forceinline__ uint32_t tf32_hi(float x) {
    uint32_t r;
    asm("cvt.rna.tf32.f32 %0, %1;" : "=r"(r) : "f"(x));
    return r;
}

__device__ __forceinline__ void mma_tf32(float* d, const uint32_t* a,
                                         uint32_t b0, uint32_t b1) {
    asm volatile(
        "mma.sync.aligned.m16n8k8.row.col.f32.tf32.tf32.f32 "
        "{%0,%1,%2,%3},{%4,%5,%6,%7},{%8,%9},{%0,%1,%2,%3};"
        : "+f"(d[0]), "+f"(d[1]), "+f"(d[2]), "+f"(d[3])
        : "r"(a[0]), "r"(a[1]), "r"(a[2]), "r"(a[3]), "r"(b0), "r"(b1));
}

// 256 threads, 8 warps (2 m x 4 n). Warp tile 64x32. BK=16 (2 k-atoms).
// Requires M % 128 == 0, K % 16 == 0. N edge guarded.
__global__ __launch_bounds__(256)
void mma3_gemm_nt(int M, int N, int K,
                  const float* __restrict__ A,
                  const float* __restrict__ B,
                  float* __restrict__ C)
{
    __shared__ float Ah[128*20], Al[128*20], Bh[128*20], Bl[128*20];

    const int tid    = threadIdx.x;
    const int lane   = tid & 31;
    const int wid    = tid >> 5;
    const int g      = lane >> 2;       // group 0..7
    const int tg     = lane & 3;        // thread-in-group 0..3
    const int warp_m = wid >> 2;        // 0..1
    const int warp_n = wid & 3;         // 0..3
    const long m0 = (long)blockIdx.y * 128;
    const long n0 = (long)blockIdx.x * 128;

    float d[4][4][4];
#pragma unroll
    for (int i = 0; i < 4; i++)
#pragma unroll
        for (int j = 0; j < 4; j++)
#pragma unroll
            for (int r = 0; r < 4; r++) d[i][j][r] = 0.f;

    // g2s mapping: tile is 128 rows x 16 k = 512 float4; 2 per thread.
    const int r0 = tid >> 2,          q0 = (tid & 3) * 4;
    const int r1 = (tid + 256) >> 2,  q1 = ((tid + 256) & 3) * 4;

    float4 ra0, ra1, rb0, rb1;
    const float4 z4 = make_float4(0.f, 0.f, 0.f, 0.f);

#define LOAD_AB(K0)                                                            \
    do {                                                                       \
        ra0 = *(const float4*)&A[(m0 + r0) * K + (K0) + q0];                   \
        ra1 = *(const float4*)&A[(m0 + r1) * K + (K0) + q1];                   \
        rb0 = (n0 + r0 < N) ? *(const float4*)&B[(n0 + r0) * K + (K0) + q0] : z4; \
        rb1 = (n0 + r1 < N) ? *(const float4*)&B[(n0 + r1) * K + (K0) + q1] : z4; \
    } while (0)

    LOAD_AB(0);

    for (int k0 = 0; k0 < K; k0 += 16) {
        // split to hi/lo and stage in smem
        {
            float4 h, l;
#define SPLIT_STORE(V, HB, LB, RR, QQ)                                         \
            h.x = __uint_as_float(tf32_hi(V.x)); l.x = V.x - h.x;              \
            h.y = __uint_as_float(tf32_hi(V.y)); l.y = V.y - h.y;              \
            h.z = __uint_as_float(tf32_hi(V.z)); l.z = V.z - h.z;              \
            h.w = __uint_as_float(tf32_hi(V.w)); l.w = V.w - h.w;              \
            *(float4*)&HB[(RR)*20 + (QQ)] = h;                                 \
            *(float4*)&LB[(RR)*20 + (QQ)] = l;
            SPLIT_STORE(ra0, Ah, Al, r0, q0);
            SPLIT_STORE(ra1, Ah, Al, r1, q1);
            SPLIT_STORE(rb0, Bh, Bl, r0, q0);
            SPLIT_STORE(rb1, Bh, Bl, r1, q1);
#undef SPLIT_STORE
        }
        __syncthreads();

        if (k0 + 16 < K) LOAD_AB(k0 + 16);

#pragma unroll
        for (int ka = 0; ka < 2; ka++) {
            const int kb = ka * 8;
            uint32_t ah[4][4], al[4][4];
#pragma unroll
            for (int ma = 0; ma < 4; ma++) {
                const int rr = warp_m * 64 + ma * 16;
                ah[ma][0] = __float_as_uint(Ah[(rr+g  )*20 + kb+tg  ]);
                ah[ma][1] = __float_as_uint(Ah[(rr+g+8)*20 + kb+tg  ]);
                ah[ma][2] = __float_as_uint(Ah[(rr+g  )*20 + kb+tg+4]);
                ah[ma][3] = __float_as_uint(Ah[(rr+g+8)*20 + kb+tg+4]);
                al[ma][0] = __float_as_uint(Al[(rr+g  )*20 + kb+tg  ]);
                al[ma][1] = __float_as_uint(Al[(rr+g+8)*20 + kb+tg  ]);
                al[ma][2] = __float_as_uint(Al[(rr+g  )*20 + kb+tg+4]);
                al[ma][3] = __float_as_uint(Al[(rr+g+8)*20 + kb+tg+4]);
            }
#pragma unroll
            for (int na = 0; na < 4; na++) {
                const int cc = warp_n * 32 + na * 8;
                const uint32_t bh0 = __float_as_uint(Bh[(cc+g)*20 + kb+tg  ]);
                const uint32_t bh1 = __float_as_uint(Bh[(cc+g)*20 + kb+tg+4]);
                const uint32_t bl0 = __float_as_uint(Bl[(cc+g)*20 + kb+tg  ]);
                const uint32_t bl1 = __float_as_uint(Bl[(cc+g)*20 + kb+tg+4]);
#pragma unroll
                for (int ma = 0; ma < 4; ma++) {
                    mma_tf32(d[ma][na], ah[ma], bh0, bh1);  // hi*hi
                    mma_tf32(d[ma][na], al[ma], bh0, bh1);  // lo*hi
                    mma_tf32(d[ma][na], ah[ma], bl0, bl1);  // hi*lo
                }
            }
        }
        __syncthreads();
    }
#undef LOAD_AB

    // epilogue
#pragma unroll
    for (int ma = 0; ma < 4; ma++) {
        const long rbase = m0 + warp_m * 64 + ma * 16;
#pragma unroll
        for (int na = 0; na < 4; na++) {
            const long col = n0 + warp_n * 32 + na * 8 + 2 * tg;
            if (col < N) {
                *(float2*)&C[(rbase + g    ) * N + col] = make_float2(d[ma][na][0], d[ma][na][1]);
                *(float2*)&C[(rbase + g + 8) * N + col] = make_float2(d[ma][na][2], d[ma][na][3]);
            }
        }
    }
}

// ---------------- conv1d(4, causal) + silu -------------------------------------
__global__ void conv_silu_kernel(const float* __restrict__ conv_w,
                                 const float* __restrict__ conv_b)
{
    int id = blockIdx.x * blockDim.x + threadIdx.x;
    if (id >= L * DI) return;
    int t = id / DI, c = id % DI;
    float acc = conv_b[c];
#pragma unroll
    for (int i = 0; i < 4; i++) {
        int ts = t + i - 3;
        if (ts >= 0)
            acc = fmaf(g_proj[(size_t)ts * NPROJ + OFF_X + c], conv_w[c*4 + i], acc);
    }
    float sig = 1.f / (1.f + expf(-acc));
    g_xconv[id] = acc * sig;
}

// ---------------- dt / Phi / exp tables ----------------------------------------
__global__ void dt_phi_kernel(const float* __restrict__ A_log,
                              const float* __restrict__ dt_bias)
{
    const int h = blockIdx.x;
    const int l = threadIdx.x;
    const float Ah   = -expf(A_log[h]);
    const float bias = dt_bias[h];
    float carry = 0.f;
    for (int c = 0; c < L/32; c++) {
        int t = c*32 + l;
        float xr = g_proj[(size_t)t * NPROJ + OFF_DT + h];
        float dt = fmaxf(xr, 0.f) + log1pf(expf(-fabsf(xr))) + bias;
        g_dt[h*L + t] = dt;
        float s = Ah * dt;
#pragma unroll
        for (int o = 1; o < 32; o <<= 1) {
            float v = __shfl_up_sync(0xffffffffu, s, o);
            if (l >= o) s += v;
        }
        float Phi = carry + s;
        g_eneg[h*L + t] = expf(fminf(-Phi, 80.f));
        g_ephi[h*L + t] = expf(Phi);
        carry = __shfl_sync(0xffffffffu, Phi, 31);
    }
}

// ---------------- SSD stage A: per-chunk state increment -----------------------
__global__ __launch_bounds__(256)
void chunk_dstate_kernel()
{
    const int h = blockIdx.x;
    const int c = blockIdx.y;
    const int t0 = c * CT;

    __shared__ float Bsh[CT][DS];
    __shared__ float Xsh[CT][HD];

    const int tid = threadIdx.x;
    for (int idx = tid*4; idx < CT*DS; idx += 256*4) {
        int u = idx / DS, j = idx % DS;
        *(float4*)&Bsh[u][j] =
            *(const float4*)&g_proj[(size_t)(t0+u)*NPROJ + OFF_B + h*DS + j];
    }
    for (int idx = tid*4; idx < CT*HD; idx += 256*4) {
        int u = idx / HD, i = idx % HD;
        float su = g_eneg[h*L + t0 + u] * g_dt[h*L + t0 + u];
        float4 xv = *(const float4*)&g_xconv[(size_t)(t0+u)*DI + h*HD + i];
        xv.x *= su; xv.y *= su; xv.z *= su; xv.w *= su;
        *(float4*)&Xsh[u][i] = xv;
    }
    __syncthreads();

    const int lane = tid & 31;
    const int ty   = tid >> 5;
    const int j0   = ty * 8;
    const int i0   = lane * 4;

    float acc[8][4];
#pragma unroll
    for (int a = 0; a < 8; a++)
#pragma unroll
        for (int b = 0; b < 4; b++) acc[a][b] = 0.f;

    for (int u = 0; u < CT; u++) {
        float4 xv = *(const float4*)&Xsh[u][i0];
#pragma unroll
        for (int a = 0; a < 8; a++) {
            float bj = Bsh[u][j0 + a];
            acc[a][0] = fmaf(bj, xv.x, acc[a][0]);
            acc[a][1] = fmaf(bj, xv.y, acc[a][1]);
            acc[a][2] = fmaf(bj, xv.z, acc[a][2]);
            acc[a][3] = fmaf(bj, xv.w, acc[a][3]);
        }
    }
    float* dst = &g_dS[((size_t)(h*NC + c)) * DS * HD];
#pragma unroll
    for (int a = 0; a < 8; a++)
        *(float4*)&dst[(j0+a)*HD + i0] = *(float4*)&acc[a][0];
}

// ---------------- SSD stage B: exclusive prefix over chunks --------------------
__global__ void state_prefix_kernel()
{
    int g = blockIdx.x * blockDim.x + threadIdx.x;
    if (g >= NH * DS * HD) return;
    int h = g / (DS*HD);
    int e = g % (DS*HD);
    float run = 0.f;
    for (int c = 0; c < NC; c++) {
        size_t idx = ((size_t)(h*NC + c)) * DS * HD + e;
        g_S[idx] = run;
        run += g_dS[idx];
    }
}

// ---------------- SSD stage C: per-chunk output --------------------------------
__global__ __launch_bounds__(256)
void ssd_output_kernel(const float* __restrict__ Dp)
{
    const int h = blockIdx.x;
    const int c = blockIdx.y;
    const int t0 = c * CT;

    __shared__ float Csh [CT][DSP];
    __shared__ float BGsh[CT][DSP];
    __shared__ float sphi[CT], scoef[CT];

    const int tid = threadIdx.x;
    for (int idx = tid*4; idx < CT*DS; idx += 256*4) {
        int u = idx / DS, j = idx % DS;
        size_t row = (size_t)(t0+u) * NPROJ;
        *(float4*)&Csh [u][j] = *(const float4*)&g_proj[row + OFF_C + h*DS + j];
        *(float4*)&BGsh[u][j] = *(const float4*)&g_proj[row + OFF_B + h*DS + j];
    }
    if (tid < CT) {
        sphi [tid] = g_ephi[h*L + t0 + tid];
        scoef[tid] = g_eneg[h*L + t0 + tid] * g_dt[h*L + t0 + tid];
    }
    __syncthreads();

    {
        const int ut = tid & 15;
        const int tt = tid >> 4;
        const int ta = tt * 4;
        const int ua = ut * 4;
        float gacc[4][4];
#pragma unroll
        for (int a = 0; a < 4; a++)
#pragma unroll
            for (int b = 0; b < 4; b++) gacc[a][b] = 0.f;
        for (int k = 0; k < DS; k++) {
            float cr[4], br[4];
#pragma unroll
            for (int a = 0; a < 4; a++) cr[a] = Csh [ta+a][k];
#pragma unroll
            for (int b = 0; b < 4; b++) br[b] = BGsh[ua+b][k];
#pragma unroll
            for (int a = 0; a < 4; a++)
#pragma unroll
                for (int b = 0; b < 4; b++)
                    gacc[a][b] = fmaf(cr[a], br[b], gacc[a][b]);
        }
        __syncthreads();
#pragma unroll
        for (int a = 0; a < 4; a++)
#pragma unroll
            for (int b = 0; b < 4; b++) {
                int t = ta + a, u = ua + b;
                float m = (t >= u) ? sphi[t] * scoef[u] : 0.f;
                BGsh[t][u] = m * gacc[a][b];
            }
        __syncthreads();
    }

    const int lane = tid & 31;
    const int tg   = tid >> 5;
    const int tb   = tg * 8;
    const int i0   = lane * 4;
    const int hbase = h * HD;
    const float dph = Dp[h];
    const float* Srow = &g_S[((size_t)(h*NC + c)) * DS * HD];

    float accI[8][4], accS[8][4];
#pragma unroll
    for (int s = 0; s < 8; s++)
#pragma unroll
        for (int b = 0; b < 4; b++) { accI[s][b] = 0.f; accS[s][b] = 0.f; }

    for (int u = 0; u < CT; u++) {
        float4 xv = *(const float4*)&g_xconv[(size_t)(t0+u)*DI + hbase + i0];
#pragma unroll
        for (int s = 0; s < 8; s++) {
            float gv = BGsh[tb+s][u];
            accI[s][0] = fmaf(gv, xv.x, accI[s][0]);
            accI[s][1] = fmaf(gv, xv.y, accI[s][1]);
            accI[s][2] = fmaf(gv, xv.z, accI[s][2]);
            accI[s][3] = fmaf(gv, xv.w, accI[s][3]);
        }
    }
    for (int j = 0; j < DS; j++) {
        float4 sv = *(const float4*)&Srow[j*HD + i0];
#pragma unroll
        for (int s = 0; s < 8; s++) {
            float cj = Csh[tb+s][j];
            accS[s][0] = fmaf(cj, sv.x, accS[s][0]);
            accS[s][1] = fmaf(cj, sv.y, accS[s][1]);
            accS[s][2] = fmaf(cj, sv.z, accS[s][2]);
            accS[s][3] = fmaf(cj, sv.w, accS[s][3]);
        }
    }
#pragma unroll
    for (int s = 0; s < 8; s++) {
        int t = tb + s;
        float p = sphi[t];
        float4 xv = *(const float4*)&g_xconv[(size_t)(t0+t)*DI + hbase + i0];
        float4 y;
        y.x = fmaf(p, accS[s][0], accI[s][0]) + dph * xv.x;
        y.y = fmaf(p, accS[s][1], accI[s][1]) + dph * xv.y;
        y.z = fmaf(p, accS[s][2], accI[s][2]) + dph * xv.z;
        y.w = fmaf(p, accS[s][3], accI[s][3]) + dph * xv.w;
        *(float4*)&g_yssm[(size_t)(t0+t)*DI + hbase + i0] = y;
    }
}

// ---------------- RMS norm + silu(z) gate --------------------------------------
__global__ void rms_gate_kernel(const float* __restrict__ norm_w)
{
    const int t = blockIdx.x;
    __shared__ float red[256];
    float s = 0.f;
    for (int c = threadIdx.x; c < DI; c += 256) {
        float v = g_yssm[(size_t)t * DI + c];
        s = fmaf(v, v, s);
    }
    red[threadIdx.x] = s;
    __syncthreads();
    for (int o = 128; o > 0; o >>= 1) {
        if (threadIdx.x < o) red[threadIdx.x] += red[threadIdx.x + o];
        __syncthreads();
    }
    float rms = rsqrtf(red[0] / (float)DI + 1e-5f);
    for (int c = threadIdx.x; c < DI; c += 256) {
        float v = g_yssm[(size_t)t * DI + c];
        float z = g_proj[(size_t)t * NPROJ + c];
        float sig = 1.f / (1.f + expf(-z));
        g_ybar[(size_t)t * DI + c] = v * rms * norm_w[c] * (z * sig);
    }
}

// ---------------- launch --------------------------------------------------------
extern "C" void kernel_launch(void* const* d_in, const int* in_sizes, int n_in,
                              void* d_out, int out_size)
{
    const float* x       = (const float*)d_in[0];
    const float* W_in    = (const float*)d_in[1];
    const float* conv_w  = (const float*)d_in[2];
    const float* conv_b  = (const float*)d_in[3];
    const float* A_log   = (const float*)d_in[4];
    const float* Dp      = (const float*)d_in[5];
    const float* dt_bias = (const float*)d_in[6];
    const float* W_out   = (const float*)d_in[7];
    const float* norm_w  = (const float*)d_in[8];
    float* out = (float*)d_out;

    float *proj_p, *ybar_p;
    cudaGetSymbolAddress((void**)&proj_p, g_proj);
    cudaGetSymbolAddress((void**)&ybar_p, g_ybar);

    // 1) proj = x @ W_in^T      (1024 x 4620 x 768) — 3xTF32 tensor cores
    mma3_gemm_nt<<<dim3((NPROJ + 127)/128, L/128), 256>>>(
        L, NPROJ, DM, x, W_in, proj_p);

    // 2) causal conv1d + silu
    conv_silu_kernel<<<(L*DI + 255)/256, 256>>>(conv_w, conv_b);

    // 3) dt / Phi / exp tables
    dt_phi_kernel<<<NH, 32>>>(A_log, dt_bias);

    // 4a) per-chunk state increments
    chunk_dstate_kernel<<<dim3(NH, NC), 256>>>();

    // 4b) exclusive chunk-state prefix
    state_prefix_kernel<<<(NH*DS*HD + 255)/256, 256>>>();

    // 4c) chunk outputs
    ssd_output_kernel<<<dim3(NH, NC), 256>>>(Dp);

    // 5) RMS norm + gate
    rms_gate_kernel<<<L, 256>>>(norm_w);

    // 6) out = ybar @ W_out^T   (1024 x 768 x 1536) — 3xTF32 tensor cores
    mma3_gemm_nt<<<dim3(DM/128, L/128), 256>>>(
        L, DM, DI, ybar_p, W_out, out);
}

// round 6
// speedup vs baseline: 1.9606x; 1.3794x over previous
#include <cuda_runtime.h>
#include <cuda_bf16.h>
#include <math.h>
#include <stdint.h>

#define L      1024
#define DM     768
#define DI     1536
#define NH     12
#define HD     128
#define DS     64
#define NPROJ  4620
#define OFF_X  1536
#define OFF_B  3072
#define OFF_C  3840
#define OFF_DT 4608
#define NC     16
#define CT     64
#define DSP    (DS + 4)

// ---------------- scratch -------------------------------------------------------
__device__ float g_proj [L * NPROJ];
__device__ float g_xconv[L * DI];
__device__ float g_dt   [NH * L];
__device__ float g_eneg [NH * L];
__device__ float g_ephi [NH * L];
__device__ float g_yssm [L * DI];
__device__ float g_ybar [L * DI];
__device__ float g_dS   [NH * NC * DS * HD];
__device__ float g_S    [NH * NC * DS * HD];
// bf16 hi/lo splits
__device__ __nv_bfloat16 g_xh [L * DM],    g_xl [L * DM];
__device__ __nv_bfloat16 g_w1h[NPROJ*DM],  g_w1l[NPROJ*DM];
__device__ __nv_bfloat16 g_yh [L * DI],    g_yl [L * DI];
__device__ __nv_bfloat16 g_w2h[DM * DI],   g_w2l[DM * DI];

// ---------------- helpers -------------------------------------------------------
__device__ __forceinline__ uint32_t smem_u32(const void* p) {
    uint32_t a;
    asm("{ .reg .u64 t; cvta.to.shared.u64 t, %1; cvt.u32.u64 %0, t; }" : "=r"(a) : "l"(p));
    return a;
}
__device__ __forceinline__ void cp16(uint32_t dst, const void* src) {
    asm volatile("cp.async.cg.shared.global [%0], [%1], 16;" :: "r"(dst), "l"(src));
}
#define CP_COMMIT() asm volatile("cp.async.commit_group;" ::: "memory")
#define CP_WAIT(n)  asm volatile("cp.async.wait_group %0;" :: "n"(n) : "memory")

__device__ __forceinline__ void mma_bf16(float* d, const uint32_t* a,
                                         uint32_t b0, uint32_t b1) {
    asm volatile(
        "mma.sync.aligned.m16n8k16.row.col.f32.bf16.bf16.f32 "
        "{%0,%1,%2,%3},{%4,%5,%6,%7},{%8,%9},{%0,%1,%2,%3};"
        : "+f"(d[0]), "+f"(d[1]), "+f"(d[2]), "+f"(d[3])
        : "r"(a[0]), "r"(a[1]), "r"(a[2]), "r"(a[3]), "r"(b0), "r"(b1));
}

// ---------------- split fp32 -> bf16 hi/lo --------------------------------------
__global__ void split_kernel(const float* __restrict__ src,
                             __nv_bfloat16* __restrict__ hi,
                             __nv_bfloat16* __restrict__ lo, int n)
{
    int i = blockIdx.x * blockDim.x + threadIdx.x;
    if (i >= n) return;
    float x = src[i];
    __nv_bfloat16 h = __float2bfloat16(x);
    hi[i] = h;
    lo[i] = __float2bfloat16(x - __bfloat162float(h));
}

// ---------------- bf16 3-term mma GEMM: C[M,N] = A[M,K]*B[N,K]^T ---------------
// 256 threads, 8 warps (2m x 4n), warp tile 64x32, block tile 128x128, BK=32.
// 2-stage cp.async pipeline. Smem row stride 40 bf16 (80 B).
// M%128==0, K%32==0. B rows clamped at the N edge (outputs col>=N never stored).
#define GSTRIDE 40
#define ARR_BYTES (128 * GSTRIDE * 2)       // 10240
#define STAGE_BYTES (4 * ARR_BYTES)         // 40960
#define GEMM_SMEM (2 * STAGE_BYTES)         // 81920

__global__ __launch_bounds__(256)
void bf16_gemm_nt(int M, int N, int K,
                  const __nv_bfloat16* __restrict__ Ahi, const __nv_bfloat16* __restrict__ Alo,
                  const __nv_bfloat16* __restrict__ Bhi, const __nv_bfloat16* __restrict__ Blo,
                  float* __restrict__ C)
{
    extern __shared__ char smem[];
    const uint32_t sb = smem_u32(smem);

    const int tid    = threadIdx.x;
    const int lane   = tid & 31;
    const int wid    = tid >> 5;
    const int g      = lane >> 2;        // 0..7
    const int tg     = lane & 3;         // 0..3
    const int warp_m = wid >> 2;         // 0..1
    const int warp_n = wid & 3;          // 0..3
    const long m0 = (long)blockIdx.y * 128;
    const long n0 = (long)blockIdx.x * 128;

    // g2s: per array 128 rows x 32 bf16 = 512 x 16B chunks, 2 per thread
    const int r0 = tid >> 1;                  // chunks tid*? -> id = tid: r=tid>>2... use two ids
    (void)r0;
    const int id0 = tid,        ra_ = id0 >> 2, ca_ = (id0 & 3) * 8;   // 8 bf16 = 16 B
    const int id1 = tid + 256,  rb_ = id1 >> 2, cb_ = (id1 & 3) * 8;

    const int nchunk = K >> 5;

    float d[4][4][4];
#pragma unroll
    for (int i = 0; i < 4; i++)
#pragma unroll
        for (int j = 0; j < 4; j++)
#pragma unroll
            for (int r = 0; r < 4; r++) d[i][j][r] = 0.f;

    auto issue_stage = [&](int kc, int stage) {
        const int k0 = kc << 5;
        const uint32_t base = sb + stage * STAGE_BYTES;
        const long nra = (n0 + ra_ < N) ? (n0 + ra_) : (N - 1);
        const long nrb = (n0 + rb_ < N) ? (n0 + rb_) : (N - 1);
        // A hi/lo
        cp16(base + 0*ARR_BYTES + ra_*80 + ca_*2, &Ahi[(m0 + ra_) * K + k0 + ca_]);
        cp16(base + 0*ARR_BYTES + rb_*80 + cb_*2, &Ahi[(m0 + rb_) * K + k0 + cb_]);
        cp16(base + 1*ARR_BYTES + ra_*80 + ca_*2, &Alo[(m0 + ra_) * K + k0 + ca_]);
        cp16(base + 1*ARR_BYTES + rb_*80 + cb_*2, &Alo[(m0 + rb_) * K + k0 + cb_]);
        // B hi/lo (row-clamped)
        cp16(base + 2*ARR_BYTES + ra_*80 + ca_*2, &Bhi[nra * K + k0 + ca_]);
        cp16(base + 2*ARR_BYTES + rb_*80 + cb_*2, &Bhi[nrb * K + k0 + cb_]);
        cp16(base + 3*ARR_BYTES + ra_*80 + ca_*2, &Blo[nra * K + k0 + ca_]);
        cp16(base + 3*ARR_BYTES + rb_*80 + cb_*2, &Blo[nrb * K + k0 + cb_]);
        CP_COMMIT();
    };

    issue_stage(0, 0);

    for (int kc = 0; kc < nchunk; kc++) {
        if (kc + 1 < nchunk) {
            issue_stage(kc + 1, (kc + 1) & 1);
            CP_WAIT(1);
        } else {
            CP_WAIT(0);
        }
        __syncthreads();

        const char* st = smem + (kc & 1) * STAGE_BYTES;
        const char* pAh = st + 0*ARR_BYTES;
        const char* pAl = st + 1*ARR_BYTES;
        const char* pBh = st + 2*ARR_BYTES;
        const char* pBl = st + 3*ARR_BYTES;

#pragma unroll
        for (int ka = 0; ka < 2; ka++) {
            const int kb = ka * 16;                    // bf16 col within 32
            uint32_t ah[4][4], al[4][4];
#pragma unroll
            for (int ma = 0; ma < 4; ma++) {
                const int rr = warp_m * 64 + ma * 16;
                const int c0 = (kb + tg * 2) * 2;      // byte col
                ah[ma][0] = *(const uint32_t*)(pAh + (rr+g  )*80 + c0);
                ah[ma][1] = *(const uint32_t*)(pAh + (rr+g+8)*80 + c0);
                ah[ma][2] = *(const uint32_t*)(pAh + (rr+g  )*80 + c0 + 16);
                ah[ma][3] = *(const uint32_t*)(pAh + (rr+g+8)*80 + c0 + 16);
                al[ma][0] = *(const uint32_t*)(pAl + (rr+g  )*80 + c0);
                al[ma][1] = *(const uint32_t*)(pAl + (rr+g+8)*80 + c0);
                al[ma][2] = *(const uint32_t*)(pAl + (rr+g  )*80 + c0 + 16);
                al[ma][3] = *(const uint32_t*)(pAl + (rr+g+8)*80 + c0 + 16);
            }
#pragma unroll
            for (int na = 0; na < 4; na++) {
                const int cc = warp_n * 32 + na * 8;
                const int c0 = (kb + tg * 2) * 2;
                const uint32_t bh0 = *(const uint32_t*)(pBh + (cc+g)*80 + c0);
                const uint32_t bh1 = *(const uint32_t*)(pBh + (cc+g)*80 + c0 + 16);
                const uint32_t bl0 = *(const uint32_t*)(pBl + (cc+g)*80 + c0);
                const uint32_t bl1 = *(const uint32_t*)(pBl + (cc+g)*80 + c0 + 16);
#pragma unroll
                for (int ma = 0; ma < 4; ma++) {
                    mma_bf16(d[ma][na], ah[ma], bh0, bh1);   // hi*hi
                    mma_bf16(d[ma][na], al[ma], bh0, bh1);   // lo*hi
                    mma_bf16(d[ma][na], ah[ma], bl0, bl1);   // hi*lo
                }
            }
        }
        __syncthreads();
    }

    // epilogue
#pragma unroll
    for (int ma = 0; ma < 4; ma++) {
        const long rbase = m0 + warp_m * 64 + ma * 16;
#pragma unroll
        for (int na = 0; na < 4; na++) {
            const long col = n0 + warp_n * 32 + na * 8 + 2 * tg;
            if (col < N) {
                *(float2*)&C[(rbase + g    ) * N + col] = make_float2(d[ma][na][0], d[ma][na][1]);
                *(float2*)&C[(rbase + g + 8) * N + col] = make_float2(d[ma][na][2], d[ma][na][3]);
            }
        }
    }
}

// ---------------- conv1d(4, causal) + silu -------------------------------------
__global__ void conv_silu_kernel(const float* __restrict__ conv_w,
                                 const float* __restrict__ conv_b)
{
    int id = blockIdx.x * blockDim.x + threadIdx.x;
    if (id >= L * DI) return;
    int t = id / DI, c = id % DI;
    float acc = conv_b[c];
#pragma unroll
    for (int i = 0; i < 4; i++) {
        int ts = t + i - 3;
        if (ts >= 0)
            acc = fmaf(g_proj[(size_t)ts * NPROJ + OFF_X + c], conv_w[c*4 + i], acc);
    }
    float sig = 1.f / (1.f + expf(-acc));
    g_xconv[id] = acc * sig;
}

// ---------------- dt / Phi / exp tables ----------------------------------------
__global__ void dt_phi_kernel(const float* __restrict__ A_log,
                              const float* __restrict__ dt_bias)
{
    const int h = blockIdx.x;
    const int l = threadIdx.x;
    const float Ah   = -expf(A_log[h]);
    const float bias = dt_bias[h];
    float carry = 0.f;
    for (int c = 0; c < L/32; c++) {
        int t = c*32 + l;
        float xr = g_proj[(size_t)t * NPROJ + OFF_DT + h];
        float dt = fmaxf(xr, 0.f) + log1pf(expf(-fabsf(xr))) + bias;
        g_dt[h*L + t] = dt;
        float s = Ah * dt;
#pragma unroll
        for (int o = 1; o < 32; o <<= 1) {
            float v = __shfl_up_sync(0xffffffffu, s, o);
            if (l >= o) s += v;
        }
        float Phi = carry + s;
        g_eneg[h*L + t] = expf(fminf(-Phi, 80.f));
        g_ephi[h*L + t] = expf(Phi);
        carry = __shfl_sync(0xffffffffu, Phi, 31);
    }
}

// ---------------- SSD stage A: per-chunk state increment -----------------------
__global__ __launch_bounds__(256)
void chunk_dstate_kernel()
{
    const int h = blockIdx.x;
    const int c = blockIdx.y;
    const int t0 = c * CT;

    __shared__ float Bsh[CT][DS];
    __shared__ float Xsh[CT][HD];

    const int tid = threadIdx.x;
    for (int idx = tid*4; idx < CT*DS; idx += 256*4) {
        int u = idx / DS, j = idx % DS;
        *(float4*)&Bsh[u][j] =
            *(const float4*)&g_proj[(size_t)(t0+u)*NPROJ + OFF_B + h*DS + j];
    }
    for (int idx = tid*4; idx < CT*HD; idx += 256*4) {
        int u = idx / HD, i = idx % HD;
        float su = g_eneg[h*L + t0 + u] * g_dt[h*L + t0 + u];
        float4 xv = *(const float4*)&g_xconv[(size_t)(t0+u)*DI + h*HD + i];
        xv.x *= su; xv.y *= su; xv.z *= su; xv.w *= su;
        *(float4*)&Xsh[u][i] = xv;
    }
    __syncthreads();

    const int lane = tid & 31;
    const int ty   = tid >> 5;
    const int j0   = ty * 8;
    const int i0   = lane * 4;

    float acc[8][4];
#pragma unroll
    for (int a = 0; a < 8; a++)
#pragma unroll
        for (int b = 0; b < 4; b++) acc[a][b] = 0.f;

    for (int u = 0; u < CT; u++) {
        float4 xv = *(const float4*)&Xsh[u][i0];
#pragma unroll
        for (int a = 0; a < 8; a++) {
            float bj = Bsh[u][j0 + a];
            acc[a][0] = fmaf(bj, xv.x, acc[a][0]);
            acc[a][1] = fmaf(bj, xv.y, acc[a][1]);
            acc[a][2] = fmaf(bj, xv.z, acc[a][2]);
            acc[a][3] = fmaf(bj, xv.w, acc[a][3]);
        }
    }
    float* dst = &g_dS[((size_t)(h*NC + c)) * DS * HD];
#pragma unroll
    for (int a = 0; a < 8; a++)
        *(float4*)&dst[(j0+a)*HD + i0] = *(float4*)&acc[a][0];
}

// ---------------- SSD stage B: exclusive prefix over chunks --------------------
__global__ void state_prefix_kernel()
{
    int g = blockIdx.x * blockDim.x + threadIdx.x;
    if (g >= NH * DS * HD) return;
    int h = g / (DS*HD);
    int e = g % (DS*HD);
    float run = 0.f;
    for (int c = 0; c < NC; c++) {
        size_t idx = ((size_t)(h*NC + c)) * DS * HD + e;
        g_S[idx] = run;
        run += g_dS[idx];
    }
}

// ---------------- SSD stage C: per-chunk output --------------------------------
__global__ __launch_bounds__(256)
void ssd_output_kernel(const float* __restrict__ Dp)
{
    const int h = blockIdx.x;
    const int c = blockIdx.y;
    const int t0 = c * CT;

    __shared__ float Csh [CT][DSP];
    __shared__ float BGsh[CT][DSP];
    __shared__ float sphi[CT], scoef[CT];

    const int tid = threadIdx.x;
    for (int idx = tid*4; idx < CT*DS; idx += 256*4) {
        int u = idx / DS, j = idx % DS;
        size_t row = (size_t)(t0+u) * NPROJ;
        *(float4*)&Csh [u][j] = *(const float4*)&g_proj[row + OFF_C + h*DS + j];
        *(float4*)&BGsh[u][j] = *(const float4*)&g_proj[row + OFF_B + h*DS + j];
    }
    if (tid < CT) {
        sphi [tid] = g_ephi[h*L + t0 + tid];
        scoef[tid] = g_eneg[h*L + t0 + tid] * g_dt[h*L + t0 + tid];
    }
    __syncthreads();

    {
        const int ut = tid & 15;
        const int tt = tid >> 4;
        const int ta = tt * 4;
        const int ua = ut * 4;
        float gacc[4][4];
#pragma unroll
        for (int a = 0; a < 4; a++)
#pragma unroll
            for (int b = 0; b < 4; b++) gacc[a][b] = 0.f;
        for (int k = 0; k < DS; k++) {
            float cr[4], br[4];
#pragma unroll
            for (int a = 0; a < 4; a++) cr[a] = Csh [ta+a][k];
#pragma unroll
            for (int b = 0; b < 4; b++) br[b] = BGsh[ua+b][k];
#pragma unroll
            for (int a = 0; a < 4; a++)
#pragma unroll
                for (int b = 0; b < 4; b++)
                    gacc[a][b] = fmaf(cr[a], br[b], gacc[a][b]);
        }
        __syncthreads();
#pragma unroll
        for (int a = 0; a < 4; a++)
#pragma unroll
            for (int b = 0; b < 4; b++) {
                int t = ta + a, u = ua + b;
                float m = (t >= u) ? sphi[t] * scoef[u] : 0.f;
                BGsh[t][u] = m * gacc[a][b];
            }
        __syncthreads();
    }

    const int lane = tid & 31;
    const int tg   = tid >> 5;
    const int tb   = tg * 8;
    const int i0   = lane * 4;
    const int hbase = h * HD;
    const float dph = Dp[h];
    const float* Srow = &g_S[((size_t)(h*NC + c)) * DS * HD];

    float accI[8][4], accS[8][4];
#pragma unroll
    for (int s = 0; s < 8; s++)
#pragma unroll
        for (int b = 0; b < 4; b++) { accI[s][b] = 0.f; accS[s][b] = 0.f; }

    for (int u = 0; u < CT; u++) {
        float4 xv = *(const float4*)&g_xconv[(size_t)(t0+u)*DI + hbase + i0];
#pragma unroll
        for (int s = 0; s < 8; s++) {
            float gv = BGsh[tb+s][u];
            accI[s][0] = fmaf(gv, xv.x, accI[s][0]);
            accI[s][1] = fmaf(gv, xv.y, accI[s][1]);
            accI[s][2] = fmaf(gv, xv.z, accI[s][2]);
            accI[s][3] = fmaf(gv, xv.w, accI[s][3]);
        }
    }
    for (int j = 0; j < DS; j++) {
        float4 sv = *(const float4*)&Srow[j*HD + i0];
#pragma unroll
        for (int s = 0; s < 8; s++) {
            float cj = Csh[tb+s][j];
            accS[s][0] = fmaf(cj, sv.x, accS[s][0]);
            accS[s][1] = fmaf(cj, sv.y, accS[s][1]);
            accS[s][2] = fmaf(cj, sv.z, accS[s][2]);
            accS[s][3] = fmaf(cj, sv.w, accS[s][3]);
        }
    }
#pragma unroll
    for (int s = 0; s < 8; s++) {
        int t = tb + s;
        float p = sphi[t];
        float4 xv = *(const float4*)&g_xconv[(size_t)(t0+t)*DI + hbase + i0];
        float4 y;
        y.x = fmaf(p, accS[s][0], accI[s][0]) + dph * xv.x;
        y.y = fmaf(p, accS[s][1], accI[s][1]) + dph * xv.y;
        y.z = fmaf(p, accS[s][2], accI[s][2]) + dph * xv.z;
        y.w = fmaf(p, accS[s][3], accI[s][3]) + dph * xv.w;
        *(float4*)&g_yssm[(size_t)(t0+t)*DI + hbase + i0] = y;
    }
}

// ---------------- RMS norm + silu(z) gate --------------------------------------
__global__ void rms_gate_kernel(const float* __restrict__ norm_w)
{
    const int t = blockIdx.x;
    __shared__ float red[256];
    float s = 0.f;
    for (int c = threadIdx.x; c < DI; c += 256) {
        float v = g_yssm[(size_t)t * DI + c];
        s = fmaf(v, v, s);
    }
    red[threadIdx.x] = s;
    __syncthreads();
    for (int o = 128; o > 0; o >>= 1) {
        if (threadIdx.x < o) red[threadIdx.x] += red[threadIdx.x + o];
        __syncthreads();
    }
    float rms = rsqrtf(red[0] / (float)DI + 1e-5f);
    for (int c = threadIdx.x; c < DI; c += 256) {
        float v = g_yssm[(size_t)t * DI + c];
        float z = g_proj[(size_t)t * NPROJ + c];
        float sig = 1.f / (1.f + expf(-z));
        g_ybar[(size_t)t * DI + c] = v * rms * norm_w[c] * (z * sig);
    }
}

// ---------------- launch --------------------------------------------------------
extern "C" void kernel_launch(void* const* d_in, const int* in_sizes, int n_in,
                              void* d_out, int out_size)
{
    const float* x       = (const float*)d_in[0];
    const float* W_in    = (const float*)d_in[1];
    const float* conv_w  = (const float*)d_in[2];
    const float* conv_b  = (const float*)d_in[3];
    const float* A_log   = (const float*)d_in[4];
    const float* Dp      = (const float*)d_in[5];
    const float* dt_bias = (const float*)d_in[6];
    const float* W_out   = (const float*)d_in[7];
    const float* norm_w  = (const float*)d_in[8];
    float* out = (float*)d_out;

    float *proj_p, *ybar_p;
    __nv_bfloat16 *xh, *xl, *w1h, *w1l, *yh, *yl, *w2h, *w2l;
    cudaGetSymbolAddress((void**)&proj_p, g_proj);
    cudaGetSymbolAddress((void**)&ybar_p, g_ybar);
    cudaGetSymbolAddress((void**)&xh,  g_xh);  cudaGetSymbolAddress((void**)&xl,  g_xl);
    cudaGetSymbolAddress((void**)&w1h, g_w1h); cudaGetSymbolAddress((void**)&w1l, g_w1l);
    cudaGetSymbolAddress((void**)&yh,  g_yh);  cudaGetSymbolAddress((void**)&yl,  g_yl);
    cudaGetSymbolAddress((void**)&w2h, g_w2h); cudaGetSymbolAddress((void**)&w2l, g_w2l);

    cudaFuncSetAttribute(bf16_gemm_nt, cudaFuncAttributeMaxDynamicSharedMemorySize, GEMM_SMEM);

    // 0) bf16 hi/lo splits for GEMM1
    split_kernel<<<(L*DM + 255)/256, 256>>>(x, xh, xl, L*DM);
    split_kernel<<<(NPROJ*DM + 255)/256, 256>>>(W_in, w1h, w1l, NPROJ*DM);

    // 1) proj = x @ W_in^T  (bf16 mma, 3-term split)
    bf16_gemm_nt<<<dim3((NPROJ + 127)/128, L/128), 256, GEMM_SMEM>>>(
        L, NPROJ, DM, xh, xl, w1h, w1l, proj_p);

    // 2) causal conv1d + silu
    conv_silu_kernel<<<(L*DI + 255)/256, 256>>>(conv_w, conv_b);

    // 3) dt / Phi / exp tables
    dt_phi_kernel<<<NH, 32>>>(A_log, dt_bias);

    // 4) SSD pipeline
    chunk_dstate_kernel<<<dim3(NH, NC), 256>>>();
    state_prefix_kernel<<<(NH*DS*HD + 255)/256, 256>>>();
    ssd_output_kernel<<<dim3(NH, NC), 256>>>(Dp);

    // 5) RMS norm + gate
    rms_gate_kernel<<<L, 256>>>(norm_w);

    // 6) splits for GEMM2 + out = ybar @ W_out^T
    split_kernel<<<(L*DI + 255)/256, 256>>>(ybar_p, yh, yl, L*DI);
    split_kernel<<<(DM*DI + 255)/256, 256>>>(W_out, w2h, w2l, DM*DI);
    bf16_gemm_nt<<<dim3(DM/128, L/128), 256, GEMM_SMEM>>>(
        L, DM, DI, yh, yl, w2h, w2l, out);
}

// round 7
// speedup vs baseline: 1.9774x; 1.0086x over previous
#include <cuda_runtime.h>
#include <cuda_bf16.h>
#include <math.h>
#include <stdint.h>

#define L      1024
#define DM     768
#define DI     1536
#define NH     12
#define HD     128
#define DS     64
#define NPROJ  4620
#define OFF_X  1536
#define OFF_B  3072
#define OFF_C  3840
#define OFF_DT 4608
#define NC     16
#define CT     64
#define DSP    (DS + 4)

// ---------------- scratch -------------------------------------------------------
__device__ float g_proj [L * NPROJ];
__device__ float g_xconv[L * DI];
__device__ float g_dt   [NH * L];
__device__ float g_eneg [NH * L];
__device__ float g_ephi [NH * L];
__device__ float g_yssm [L * DI];
__device__ float g_dS   [NH * NC * DS * HD];
__device__ float g_S    [NH * NC * DS * HD];
__device__ __nv_bfloat16 g_xh [L * DM],    g_xl [L * DM];
__device__ __nv_bfloat16 g_w1h[NPROJ*DM],  g_w1l[NPROJ*DM];
__device__ __nv_bfloat16 g_yh [L * DI],    g_yl [L * DI];
__device__ __nv_bfloat16 g_w2h[DM * DI],   g_w2l[DM * DI];

// ---------------- helpers -------------------------------------------------------
__device__ __forceinline__ uint32_t smem_u32(const void* p) {
    uint32_t a;
    asm("{ .reg .u64 t; cvta.to.shared.u64 t, %1; cvt.u32.u64 %0, t; }" : "=r"(a) : "l"(p));
    return a;
}
__device__ __forceinline__ void cp16(uint32_t dst, const void* src) {
    asm volatile("cp.async.cg.shared.global [%0], [%1], 16;" :: "r"(dst), "l"(src));
}
#define CP_COMMIT() asm volatile("cp.async.commit_group;" ::: "memory")
#define CP_WAIT(n)  asm volatile("cp.async.wait_group %0;" :: "n"(n) : "memory")

__device__ __forceinline__ void mma_bf16(float* d, const uint32_t* a,
                                         uint32_t b0, uint32_t b1) {
    asm volatile(
        "mma.sync.aligned.m16n8k16.row.col.f32.bf16.bf16.f32 "
        "{%0,%1,%2,%3},{%4,%5,%6,%7},{%8,%9},{%0,%1,%2,%3};"
        : "+f"(d[0]), "+f"(d[1]), "+f"(d[2]), "+f"(d[3])
        : "r"(a[0]), "r"(a[1]), "r"(a[2]), "r"(a[3]), "r"(b0), "r"(b1));
}
__device__ __forceinline__ void ldsm4(uint32_t* r, uint32_t addr) {
    asm volatile("ldmatrix.sync.aligned.m8n8.x4.shared.b16 {%0,%1,%2,%3}, [%4];"
                 : "=r"(r[0]), "=r"(r[1]), "=r"(r[2]), "=r"(r[3]) : "r"(addr));
}

// ---------------- split fp32 -> bf16 hi/lo --------------------------------------
__global__ void split_kernel(const float* __restrict__ src,
                             __nv_bfloat16* __restrict__ hi,
                             __nv_bfloat16* __restrict__ lo, int n)
{
    int i = blockIdx.x * blockDim.x + threadIdx.x;
    if (i >= n) return;
    float x = src[i];
    __nv_bfloat16 h = __float2bfloat16(x);
    hi[i] = h;
    lo[i] = __float2bfloat16(x - __bfloat162float(h));
}

// ---------------- bf16 3-term mma GEMM, ldmatrix + 3-stage cp.async -------------
// block 128x128, BK=32, 8 warps (2m x 4n), warp tile 64x32.
// smem row stride 40 bf16 (80B). M%128==0, K%32==0, B rows clamped at N edge.
#define GSTRIDE_B 80
#define ARR_BYTES (128 * GSTRIDE_B)         // 10240
#define STAGE_BYTES (4 * ARR_BYTES)         // 40960
#define NSTAGE 3
#define GEMM_SMEM (NSTAGE * STAGE_BYTES)    // 122880

__global__ __launch_bounds__(256)
void bf16_gemm_nt(int M, int N, int K,
                  const __nv_bfloat16* __restrict__ Ahi, const __nv_bfloat16* __restrict__ Alo,
                  const __nv_bfloat16* __restrict__ Bhi, const __nv_bfloat16* __restrict__ Blo,
                  float* __restrict__ C)
{
    extern __shared__ char smem[];
    const uint32_t sb = smem_u32(smem);

    const int tid    = threadIdx.x;
    const int lane   = tid & 31;
    const int wid    = tid >> 5;
    const int g      = lane >> 2;
    const int tg     = lane & 3;
    const int lr     = lane & 7;        // ldmatrix row-in-phase
    const int q      = lane >> 3;       // ldmatrix phase 0..3
    const int warp_m = wid >> 2;
    const int warp_n = wid & 3;
    const long m0 = (long)blockIdx.y * 128;
    const long n0 = (long)blockIdx.x * 128;

    // ldmatrix per-lane byte offsets (relative to array base within a stage)
    // A tile ma, ka: rows rr+lr+(q&1)*8, col bytes ka*32 + (q>>1)*16
    uint32_t aoff[4][2];
#pragma unroll
    for (int ma = 0; ma < 4; ma++) {
        const int rr = warp_m * 64 + ma * 16;
#pragma unroll
        for (int ka = 0; ka < 2; ka++)
            aoff[ma][ka] = (uint32_t)((rr + lr + (q & 1) * 8) * GSTRIDE_B + ka * 32 + (q >> 1) * 16);
    }
    // B pair na2 (covers n-tiles 2*na2, 2*na2+1), ka: rows cc+lr+(q>>1)*8, col ka*32+(q&1)*16
    uint32_t boff[2][2];
#pragma unroll
    for (int na2 = 0; na2 < 2; na2++) {
        const int cc = warp_n * 32 + na2 * 16;
#pragma unroll
        for (int ka = 0; ka < 2; ka++)
            boff[na2][ka] = (uint32_t)((cc + lr + (q >> 1) * 8) * GSTRIDE_B + ka * 32 + (q & 1) * 16);
    }

    // g2s: per array 128 rows x 32 bf16 = 512 x 16B; 2 chunks per thread
    const int id0 = tid,       ra_ = id0 >> 2, ca_ = (id0 & 3) * 8;
    const int id1 = tid + 256, rb_ = id1 >> 2, cb_ = (id1 & 3) * 8;
    const int nchunk = K >> 5;

    float d[4][4][4];
#pragma unroll
    for (int i = 0; i < 4; i++)
#pragma unroll
        for (int j = 0; j < 4; j++)
#pragma unroll
            for (int r = 0; r < 4; r++) d[i][j][r] = 0.f;

    auto issue_stage = [&](int kc) {
        const int k0 = kc << 5;
        const uint32_t base = sb + (kc % NSTAGE) * STAGE_BYTES;
        const long nra = (n0 + ra_ < N) ? (n0 + ra_) : (N - 1);
        const long nrb = (n0 + rb_ < N) ? (n0 + rb_) : (N - 1);
        cp16(base + 0*ARR_BYTES + ra_*GSTRIDE_B + ca_*2, &Ahi[(m0 + ra_) * K + k0 + ca_]);
        cp16(base + 0*ARR_BYTES + rb_*GSTRIDE_B + cb_*2, &Ahi[(m0 + rb_) * K + k0 + cb_]);
        cp16(base + 1*ARR_BYTES + ra_*GSTRIDE_B + ca_*2, &Alo[(m0 + ra_) * K + k0 + ca_]);
        cp16(base + 1*ARR_BYTES + rb_*GSTRIDE_B + cb_*2, &Alo[(m0 + rb_) * K + k0 + cb_]);
        cp16(base + 2*ARR_BYTES + ra_*GSTRIDE_B + ca_*2, &Bhi[nra * K + k0 + ca_]);
        cp16(base + 2*ARR_BYTES + rb_*GSTRIDE_B + cb_*2, &Bhi[nrb * K + k0 + cb_]);
        cp16(base + 3*ARR_BYTES + ra_*GSTRIDE_B + ca_*2, &Blo[nra * K + k0 + ca_]);
        cp16(base + 3*ARR_BYTES + rb_*GSTRIDE_B + cb_*2, &Blo[nrb * K + k0 + cb_]);
        CP_COMMIT();
    };

    issue_stage(0);
    if (nchunk > 1) issue_stage(1);

    for (int kc = 0; kc < nchunk; kc++) {
        __syncthreads();                       // prev readers done before overwrite
        if (kc + 2 < nchunk) { issue_stage(kc + 2); CP_WAIT(2); }
        else if (kc + 1 < nchunk) { CP_WAIT(1); }
        else { CP_WAIT(0); }
        __syncthreads();

        const uint32_t st  = sb + (kc % NSTAGE) * STAGE_BYTES;
        const uint32_t pAh = st + 0*ARR_BYTES;
        const uint32_t pAl = st + 1*ARR_BYTES;
        const uint32_t pBh = st + 2*ARR_BYTES;
        const uint32_t pBl = st + 3*ARR_BYTES;

#pragma unroll
        for (int ka = 0; ka < 2; ka++) {
            uint32_t ah[4][4], al[4][4];
#pragma unroll
            for (int ma = 0; ma < 4; ma++) {
                ldsm4(ah[ma], pAh + aoff[ma][ka]);
                ldsm4(al[ma], pAl + aoff[ma][ka]);
            }
            uint32_t bh[4][2], bl[4][2];
#pragma unroll
            for (int na2 = 0; na2 < 2; na2++) {
                uint32_t th[4], tl[4];
                ldsm4(th, pBh + boff[na2][ka]);
                ldsm4(tl, pBl + boff[na2][ka]);
                bh[na2*2][0] = th[0]; bh[na2*2][1] = th[1];
                bh[na2*2+1][0] = th[2]; bh[na2*2+1][1] = th[3];
                bl[na2*2][0] = tl[0]; bl[na2*2][1] = tl[1];
                bl[na2*2+1][0] = tl[2]; bl[na2*2+1][1] = tl[3];
            }
#pragma unroll
            for (int na = 0; na < 4; na++)
#pragma unroll
                for (int ma = 0; ma < 4; ma++) {
                    mma_bf16(d[ma][na], ah[ma], bh[na][0], bh[na][1]);
                    mma_bf16(d[ma][na], al[ma], bh[na][0], bh[na][1]);
                    mma_bf16(d[ma][na], ah[ma], bl[na][0], bl[na][1]);
                }
        }
    }

    // epilogue
#pragma unroll
    for (int ma = 0; ma < 4; ma++) {
        const long rbase = m0 + warp_m * 64 + ma * 16;
#pragma unroll
        for (int na = 0; na < 4; na++) {
            const long col = n0 + warp_n * 32 + na * 8 + 2 * tg;
            if (col < N) {
                *(float2*)&C[(rbase + g    ) * N + col] = make_float2(d[ma][na][0], d[ma][na][1]);
                *(float2*)&C[(rbase + g + 8) * N + col] = make_float2(d[ma][na][2], d[ma][na][3]);
            }
        }
    }
}

// ---------------- conv1d(4, causal) + silu -------------------------------------
__global__ void conv_silu_kernel(const float* __restrict__ conv_w,
                                 const float* __restrict__ conv_b)
{
    int id = blockIdx.x * blockDim.x + threadIdx.x;
    if (id >= L * DI) return;
    int t = id / DI, c = id % DI;
    float acc = conv_b[c];
#pragma unroll
    for (int i = 0; i < 4; i++) {
        int ts = t + i - 3;
        if (ts >= 0)
            acc = fmaf(g_proj[(size_t)ts * NPROJ + OFF_X + c], conv_w[c*4 + i], acc);
    }
    float sig = 1.f / (1.f + expf(-acc));
    g_xconv[id] = acc * sig;
}

// ---------------- dt / Phi / exp tables ----------------------------------------
__global__ void dt_phi_kernel(const float* __restrict__ A_log,
                              const float* __restrict__ dt_bias)
{
    const int h = blockIdx.x;
    const int l = threadIdx.x;
    const float Ah   = -expf(A_log[h]);
    const float bias = dt_bias[h];
    float carry = 0.f;
    for (int c = 0; c < L/32; c++) {
        int t = c*32 + l;
        float xr = g_proj[(size_t)t * NPROJ + OFF_DT + h];
        float dt = fmaxf(xr, 0.f) + log1pf(expf(-fabsf(xr))) + bias;
        g_dt[h*L + t] = dt;
        float s = Ah * dt;
#pragma unroll
        for (int o = 1; o < 32; o <<= 1) {
            float v = __shfl_up_sync(0xffffffffu, s, o);
            if (l >= o) s += v;
        }
        float Phi = carry + s;
        g_eneg[h*L + t] = expf(fminf(-Phi, 80.f));
        g_ephi[h*L + t] = expf(Phi);
        carry = __shfl_sync(0xffffffffu, Phi, 31);
    }
}

// ---------------- SSD stage A ---------------------------------------------------
__global__ __launch_bounds__(256)
void chunk_dstate_kernel()
{
    const int h = blockIdx.x;
    const int c = blockIdx.y;
    const int t0 = c * CT;

    __shared__ float Bsh[CT][DS];
    __shared__ float Xsh[CT][HD];

    const int tid = threadIdx.x;
    for (int idx = tid*4; idx < CT*DS; idx += 256*4) {
        int u = idx / DS, j = idx % DS;
        *(float4*)&Bsh[u][j] =
            *(const float4*)&g_proj[(size_t)(t0+u)*NPROJ + OFF_B + h*DS + j];
    }
    for (int idx = tid*4; idx < CT*HD; idx += 256*4) {
        int u = idx / HD, i = idx % HD;
        float su = g_eneg[h*L + t0 + u] * g_dt[h*L + t0 + u];
        float4 xv = *(const float4*)&g_xconv[(size_t)(t0+u)*DI + h*HD + i];
        xv.x *= su; xv.y *= su; xv.z *= su; xv.w *= su;
        *(float4*)&Xsh[u][i] = xv;
    }
    __syncthreads();

    const int lane = tid & 31;
    const int ty   = tid >> 5;
    const int j0   = ty * 8;
    const int i0   = lane * 4;

    float acc[8][4];
#pragma unroll
    for (int a = 0; a < 8; a++)
#pragma unroll
        for (int b = 0; b < 4; b++) acc[a][b] = 0.f;

    for (int u = 0; u < CT; u++) {
        float4 xv = *(const float4*)&Xsh[u][i0];
#pragma unroll
        for (int a = 0; a < 8; a++) {
            float bj = Bsh[u][j0 + a];
            acc[a][0] = fmaf(bj, xv.x, acc[a][0]);
            acc[a][1] = fmaf(bj, xv.y, acc[a][1]);
            acc[a][2] = fmaf(bj, xv.z, acc[a][2]);
            acc[a][3] = fmaf(bj, xv.w, acc[a][3]);
        }
    }
    float* dst = &g_dS[((size_t)(h*NC + c)) * DS * HD];
#pragma unroll
    for (int a = 0; a < 8; a++)
        *(float4*)&dst[(j0+a)*HD + i0] = *(float4*)&acc[a][0];
}

// ---------------- SSD stage B ---------------------------------------------------
__global__ void state_prefix_kernel()
{
    int g = blockIdx.x * blockDim.x + threadIdx.x;
    if (g >= NH * DS * HD) return;
    int h = g / (DS*HD);
    int e = g % (DS*HD);
    float run = 0.f;
    for (int c = 0; c < NC; c++) {
        size_t idx = ((size_t)(h*NC + c)) * DS * HD + e;
        g_S[idx] = run;
        run += g_dS[idx];
    }
}

// ---------------- SSD stage C ---------------------------------------------------
__global__ __launch_bounds__(256)
void ssd_output_kernel(const float* __restrict__ Dp)
{
    const int h = blockIdx.x;
    const int c = blockIdx.y;
    const int t0 = c * CT;

    __shared__ float Csh [CT][DSP];
    __shared__ float BGsh[CT][DSP];
    __shared__ float sphi[CT], scoef[CT];

    const int tid = threadIdx.x;
    for (int idx = tid*4; idx < CT*DS; idx += 256*4) {
        int u = idx / DS, j = idx % DS;
        size_t row = (size_t)(t0+u) * NPROJ;
        *(float4*)&Csh [u][j] = *(const float4*)&g_proj[row + OFF_C + h*DS + j];
        *(float4*)&BGsh[u][j] = *(const float4*)&g_proj[row + OFF_B + h*DS + j];
    }
    if (tid < CT) {
        sphi [tid] = g_ephi[h*L + t0 + tid];
        scoef[tid] = g_eneg[h*L + t0 + tid] * g_dt[h*L + t0 + tid];
    }
    __syncthreads();

    {
        const int ut = tid & 15;
        const int tt = tid >> 4;
        const int ta = tt * 4;
        const int ua = ut * 4;
        float gacc[4][4];
#pragma unroll
        for (int a = 0; a < 4; a++)
#pragma unroll
            for (int b = 0; b < 4; b++) gacc[a][b] = 0.f;
        for (int k = 0; k < DS; k++) {
            float cr[4], br[4];
#pragma unroll
            for (int a = 0; a < 4; a++) cr[a] = Csh [ta+a][k];
#pragma unroll
            for (int b = 0; b < 4; b++) br[b] = BGsh[ua+b][k];
#pragma unroll
            for (int a = 0; a < 4; a++)
#pragma unroll
                for (int b = 0; b < 4; b++)
                    gacc[a][b] = fmaf(cr[a], br[b], gacc[a][b]);
        }
        __syncthreads();
#pragma unroll
        for (int a = 0; a < 4; a++)
#pragma unroll
            for (int b = 0; b < 4; b++) {
                int t = ta + a, u = ua + b;
                float m = (t >= u) ? sphi[t] * scoef[u] : 0.f;
                BGsh[t][u] = m * gacc[a][b];
            }
        __syncthreads();
    }

    const int lane = tid & 31;
    const int tg   = tid >> 5;
    const int tb   = tg * 8;
    const int i0   = lane * 4;
    const int hbase = h * HD;
    const float dph = Dp[h];
    const float* Srow = &g_S[((size_t)(h*NC + c)) * DS * HD];

    float accI[8][4], accS[8][4];
#pragma unroll
    for (int s = 0; s < 8; s++)
#pragma unroll
        for (int b = 0; b < 4; b++) { accI[s][b] = 0.f; accS[s][b] = 0.f; }

    for (int u = 0; u < CT; u++) {
        float4 xv = *(const float4*)&g_xconv[(size_t)(t0+u)*DI + hbase + i0];
#pragma unroll
        for (int s = 0; s < 8; s++) {
            float gv = BGsh[tb+s][u];
            accI[s][0] = fmaf(gv, xv.x, accI[s][0]);
            accI[s][1] = fmaf(gv, xv.y, accI[s][1]);
            accI[s][2] = fmaf(gv, xv.z, accI[s][2]);
            accI[s][3] = fmaf(gv, xv.w, accI[s][3]);
        }
    }
    for (int j = 0; j < DS; j++) {
        float4 sv = *(const float4*)&Srow[j*HD + i0];
#pragma unroll
        for (int s = 0; s < 8; s++) {
            float cj = Csh[tb+s][j];
            accS[s][0] = fmaf(cj, sv.x, accS[s][0]);
            accS[s][1] = fmaf(cj, sv.y, accS[s][1]);
            accS[s][2] = fmaf(cj, sv.z, accS[s][2]);
            accS[s][3] = fmaf(cj, sv.w, accS[s][3]);
        }
    }
#pragma unroll
    for (int s = 0; s < 8; s++) {
        int t = tb + s;
        float p = sphi[t];
        float4 xv = *(const float4*)&g_xconv[(size_t)(t0+t)*DI + hbase + i0];
        float4 y;
        y.x = fmaf(p, accS[s][0], accI[s][0]) + dph * xv.x;
        y.y = fmaf(p, accS[s][1], accI[s][1]) + dph * xv.y;
        y.z = fmaf(p, accS[s][2], accI[s][2]) + dph * xv.z;
        y.w = fmaf(p, accS[s][3], accI[s][3]) + dph * xv.w;
        *(float4*)&g_yssm[(size_t)(t0+t)*DI + hbase + i0] = y;
    }
}

// ---------------- RMS norm + silu(z) gate + bf16 split (fused) ------------------
__global__ void rms_gate_kernel(const float* __restrict__ norm_w)
{
    const int t = blockIdx.x;
    __shared__ float red[256];
    float s = 0.f;
    for (int c = threadIdx.x; c < DI; c += 256) {
        float v = g_yssm[(size_t)t * DI + c];
        s = fmaf(v, v, s);
    }
    red[threadIdx.x] = s;
    __syncthreads();
    for (int o = 128; o > 0; o >>= 1) {
        if (threadIdx.x < o) red[threadIdx.x] += red[threadIdx.x + o];
        __syncthreads();
    }
    float rms = rsqrtf(red[0] / (float)DI + 1e-5f);
    for (int c = threadIdx.x; c < DI; c += 256) {
        float v = g_yssm[(size_t)t * DI + c];
        float z = g_proj[(size_t)t * NPROJ + c];
        float sig = 1.f / (1.f + expf(-z));
        float yb = v * rms * norm_w[c] * (z * sig);
        __nv_bfloat16 h = __float2bfloat16(yb);
        g_yh[(size_t)t * DI + c] = h;
        g_yl[(size_t)t * DI + c] = __float2bfloat16(yb - __bfloat162float(h));
    }
}

// ---------------- launch --------------------------------------------------------
extern "C" void kernel_launch(void* const* d_in, const int* in_sizes, int n_in,
                              void* d_out, int out_size)
{
    const float* x       = (const float*)d_in[0];
    const float* W_in    = (const float*)d_in[1];
    const float* conv_w  = (const float*)d_in[2];
    const float* conv_b  = (const float*)d_in[3];
    const float* A_log   = (const float*)d_in[4];
    const float* Dp      = (const float*)d_in[5];
    const float* dt_bias = (const float*)d_in[6];
    const float* W_out   = (const float*)d_in[7];
    const float* norm_w  = (const float*)d_in[8];
    float* out = (float*)d_out;

    float *proj_p;
    __nv_bfloat16 *xh, *xl, *w1h, *w1l, *yh, *yl, *w2h, *w2l;
    cudaGetSymbolAddress((void**)&proj_p, g_proj);
    cudaGetSymbolAddress((void**)&xh,  g_xh);  cudaGetSymbolAddress((void**)&xl,  g_xl);
    cudaGetSymbolAddress((void**)&w1h, g_w1h); cudaGetSymbolAddress((void**)&w1l, g_w1l);
    cudaGetSymbolAddress((void**)&yh,  g_yh);  cudaGetSymbolAddress((void**)&yl,  g_yl);
    cudaGetSymbolAddress((void**)&w2h, g_w2h); cudaGetSymbolAddress((void**)&w2l, g_w2l);

    cudaFuncSetAttribute(bf16_gemm_nt, cudaFuncAttributeMaxDynamicSharedMemorySize, GEMM_SMEM);

    // 0) bf16 hi/lo splits for GEMM1 + W_out (input-only, independent)
    split_kernel<<<(L*DM + 255)/256, 256>>>(x, xh, xl, L*DM);
    split_kernel<<<(NPROJ*DM + 255)/256, 256>>>(W_in, w1h, w1l, NPROJ*DM);
    split_kernel<<<(DM*DI + 255)/256, 256>>>(W_out, w2h, w2l, DM*DI);

    // 1) proj = x @ W_in^T
    bf16_gemm_nt<<<dim3((NPROJ + 127)/128, L/128), 256, GEMM_SMEM>>>(
        L, NPROJ, DM, xh, xl, w1h, w1l, proj_p);

    // 2) causal conv1d + silu
    conv_silu_kernel<<<(L*DI + 255)/256, 256>>>(conv_w, conv_b);

    // 3) dt / Phi / exp tables
    dt_phi_kernel<<<NH, 32>>>(A_log, dt_bias);

    // 4) SSD pipeline
    chunk_dstate_kernel<<<dim3(NH, NC), 256>>>();
    state_prefix_kernel<<<(NH*DS*HD + 255)/256, 256>>>();
    ssd_output_kernel<<<dim3(NH, NC), 256>>>(Dp);

    // 5) RMS norm + gate + split (fused)
    rms_gate_kernel<<<L, 256>>>(norm_w);

    // 6) out = ybar @ W_out^T
    bf16_gemm_nt<<<dim3(DM/128, L/128), 256, GEMM_SMEM>>>(
        L, DM, DI, yh, yl, w2h, w2l, out);
}

// round 8
// speedup vs baseline: 2.4349x; 1.2313x over previous
#include <cuda_runtime.h>
#include <cuda_bf16.h>
#include <math.h>
#include <stdint.h>

#define L      1024
#define DM     768
#define DI     1536
#define NH     12
#define HD     128
#define DS     64
#define NPROJ  4620
#define OFF_X  1536
#define OFF_B  3072
#define OFF_C  3840
#define OFF_DT 4608
#define NC     16
#define CT     64
#define DSP    (DS + 4)

// ---------------- scratch -------------------------------------------------------
__device__ float g_proj [L * NPROJ];
__device__ float g_xconv[L * DI];
__device__ float g_dt   [NH * L];
__device__ float g_eneg [NH * L];
__device__ float g_ephi [NH * L];
__device__ float g_yssm [L * DI];
__device__ float g_dS   [NH * NC * DS * HD];
__device__ float g_S    [NH * NC * DS * HD];
__device__ __nv_bfloat16 g_xh [L * DM],    g_xl [L * DM];
__device__ __nv_bfloat16 g_w1h[NPROJ*DM],  g_w1l[NPROJ*DM];
__device__ __nv_bfloat16 g_yh [L * DI],    g_yl [L * DI];
__device__ __nv_bfloat16 g_w2h[DM * DI],   g_w2l[DM * DI];

// ---------------- helpers -------------------------------------------------------
__device__ __forceinline__ uint32_t smem_u32(const void* p) {
    uint32_t a;
    asm("{ .reg .u64 t; cvta.to.shared.u64 t, %1; cvt.u32.u64 %0, t; }" : "=r"(a) : "l"(p));
    return a;
}
__device__ __forceinline__ void cp16(uint32_t dst, const void* src) {
    asm volatile("cp.async.cg.shared.global [%0], [%1], 16;" :: "r"(dst), "l"(src));
}
#define CP_COMMIT() asm volatile("cp.async.commit_group;" ::: "memory")
#define CP_WAIT(n)  asm volatile("cp.async.wait_group %0;" :: "n"(n) : "memory")

__device__ __forceinline__ void mma_bf16(float* d, const uint32_t* a,
                                         uint32_t b0, uint32_t b1) {
    asm volatile(
        "mma.sync.aligned.m16n8k16.row.col.f32.bf16.bf16.f32 "
        "{%0,%1,%2,%3},{%4,%5,%6,%7},{%8,%9},{%0,%1,%2,%3};"
        : "+f"(d[0]), "+f"(d[1]), "+f"(d[2]), "+f"(d[3])
        : "r"(a[0]), "r"(a[1]), "r"(a[2]), "r"(a[3]), "r"(b0), "r"(b1));
}
__device__ __forceinline__ void ldsm4(uint32_t* r, uint32_t addr) {
    asm volatile("ldmatrix.sync.aligned.m8n8.x4.shared.b16 {%0,%1,%2,%3}, [%4];"
                 : "=r"(r[0]), "=r"(r[1]), "=r"(r[2]), "=r"(r[3]) : "r"(addr));
}

// ---------------- split fp32 -> bf16 hi/lo --------------------------------------
__global__ void split_kernel(const float* __restrict__ src,
                             __nv_bfloat16* __restrict__ hi,
                             __nv_bfloat16* __restrict__ lo, int n)
{
    int i = blockIdx.x * blockDim.x + threadIdx.x;
    if (i >= n) return;
    float x = src[i];
    __nv_bfloat16 h = __float2bfloat16(x);
    hi[i] = h;
    lo[i] = __float2bfloat16(x - __bfloat162float(h));
}

// ---------------- bf16 3-term mma GEMM (term-interleaved) -----------------------
// Template MA = m16-tiles per warp (4 -> 128-row blocks, 2 -> 64-row blocks).
// 8 warps (2m x 4n), BK=32, 3-stage cp.async, smem row stride 40 bf16 (80B).
// M % (32*MA) == 0, K % 32 == 0. B rows clamped at N edge.
#define GSTRIDE_B 80
#define ARR_B_BYTES (128 * GSTRIDE_B)        // 10240

template<int MA>
__global__ __launch_bounds__(256)
void bf16_gemm_nt(int M, int N, int K,
                  const __nv_bfloat16* __restrict__ Ahi, const __nv_bfloat16* __restrict__ Alo,
                  const __nv_bfloat16* __restrict__ Bhi, const __nv_bfloat16* __restrict__ Blo,
                  float* __restrict__ C)
{
    constexpr int BM        = 32 * MA;
    constexpr int ARR_A     = BM * GSTRIDE_B;
    constexpr int STAGE     = 2 * ARR_A + 2 * ARR_B_BYTES;
    constexpr int OFF_AH    = 0;
    constexpr int OFF_AL    = ARR_A;
    constexpr int OFF_BH    = 2 * ARR_A;
    constexpr int OFF_BL    = 2 * ARR_A + ARR_B_BYTES;

    extern __shared__ char smem[];
    const uint32_t sb = smem_u32(smem);

    const int tid    = threadIdx.x;
    const int lane   = tid & 31;
    const int wid    = tid >> 5;
    const int g      = lane >> 2;
    const int tg     = lane & 3;
    const int lr     = lane & 7;
    const int q      = lane >> 3;
    const int warp_m = wid >> 2;
    const int warp_n = wid & 3;
    const long m0 = (long)blockIdx.y * BM;
    const long n0 = (long)blockIdx.x * 128;

    uint32_t aoff[MA][2];
#pragma unroll
    for (int ma = 0; ma < MA; ma++) {
        const int rr = warp_m * (MA * 16) + ma * 16;
#pragma unroll
        for (int ka = 0; ka < 2; ka++)
            aoff[ma][ka] = (uint32_t)((rr + lr + (q & 1) * 8) * GSTRIDE_B + ka * 32 + (q >> 1) * 16);
    }
    uint32_t boff[2][2];
#pragma unroll
    for (int na2 = 0; na2 < 2; na2++) {
        const int cc = warp_n * 32 + na2 * 16;
#pragma unroll
        for (int ka = 0; ka < 2; ka++)
            boff[na2][ka] = (uint32_t)((cc + lr + (q >> 1) * 8) * GSTRIDE_B + ka * 32 + (q & 1) * 16);
    }

    const int nchunk = K >> 5;

    float d[MA][4][4];
#pragma unroll
    for (int i = 0; i < MA; i++)
#pragma unroll
        for (int j = 0; j < 4; j++)
#pragma unroll
            for (int r = 0; r < 4; r++) d[i][j][r] = 0.f;

    auto issue_stage = [&](int kc) {
        const int k0 = kc << 5;
        const uint32_t base = sb + (kc % 3) * STAGE;
        // A tiles: BM rows x 32 bf16 = 4*BM 16B-chunks
#pragma unroll
        for (int c = tid; c < 4 * BM; c += 256) {
            const int r = c >> 2, col = (c & 3) * 8;
            cp16(base + OFF_AH + r*GSTRIDE_B + col*2, &Ahi[(m0 + r) * K + k0 + col]);
            cp16(base + OFF_AL + r*GSTRIDE_B + col*2, &Alo[(m0 + r) * K + k0 + col]);
        }
        // B tiles: 128 rows x 32 bf16
#pragma unroll
        for (int c = tid; c < 512; c += 256) {
            const int r = c >> 2, col = (c & 3) * 8;
            const long nr = (n0 + r < N) ? (n0 + r) : (N - 1);
            cp16(base + OFF_BH + r*GSTRIDE_B + col*2, &Bhi[nr * K + k0 + col]);
            cp16(base + OFF_BL + r*GSTRIDE_B + col*2, &Blo[nr * K + k0 + col]);
        }
        CP_COMMIT();
    };

    issue_stage(0);
    if (nchunk > 1) issue_stage(1);

    for (int kc = 0; kc < nchunk; kc++) {
        __syncthreads();
        if (kc + 2 < nchunk) { issue_stage(kc + 2); CP_WAIT(2); }
        else if (kc + 1 < nchunk) { CP_WAIT(1); }
        else { CP_WAIT(0); }
        __syncthreads();

        const uint32_t st  = sb + (kc % 3) * STAGE;
        const uint32_t pAh = st + OFF_AH;
        const uint32_t pAl = st + OFF_AL;
        const uint32_t pBh = st + OFF_BH;
        const uint32_t pBl = st + OFF_BL;

#pragma unroll
        for (int ka = 0; ka < 2; ka++) {
            uint32_t ah[MA][4], al[MA][4];
#pragma unroll
            for (int ma = 0; ma < MA; ma++) {
                ldsm4(ah[ma], pAh + aoff[ma][ka]);
                ldsm4(al[ma], pAl + aoff[ma][ka]);
            }
            uint32_t bh[4][2], bl[4][2];
#pragma unroll
            for (int na2 = 0; na2 < 2; na2++) {
                uint32_t th[4], tl[4];
                ldsm4(th, pBh + boff[na2][ka]);
                ldsm4(tl, pBl + boff[na2][ka]);
                bh[na2*2][0] = th[0]; bh[na2*2][1] = th[1];
                bh[na2*2+1][0] = th[2]; bh[na2*2+1][1] = th[3];
                bl[na2*2][0] = tl[0]; bl[na2*2][1] = tl[1];
                bl[na2*2+1][0] = tl[2]; bl[na2*2+1][1] = tl[3];
            }
            // term-interleaved: dependent MMAs per accumulator are 4*MA apart
#pragma unroll
            for (int na = 0; na < 4; na++)
#pragma unroll
                for (int ma = 0; ma < MA; ma++)
                    mma_bf16(d[ma][na], ah[ma], bh[na][0], bh[na][1]);   // hi*hi
#pragma unroll
            for (int na = 0; na < 4; na++)
#pragma unroll
                for (int ma = 0; ma < MA; ma++)
                    mma_bf16(d[ma][na], al[ma], bh[na][0], bh[na][1]);   // lo*hi
#pragma unroll
            for (int na = 0; na < 4; na++)
#pragma unroll
                for (int ma = 0; ma < MA; ma++)
                    mma_bf16(d[ma][na], ah[ma], bl[na][0], bl[na][1]);   // hi*lo
        }
    }

    // epilogue
#pragma unroll
    for (int ma = 0; ma < MA; ma++) {
        const long rbase = m0 + warp_m * (MA * 16) + ma * 16;
#pragma unroll
        for (int na = 0; na < 4; na++) {
            const long col = n0 + warp_n * 32 + na * 8 + 2 * tg;
            if (col < N) {
                *(float2*)&C[(rbase + g    ) * N + col] = make_float2(d[ma][na][0], d[ma][na][1]);
                *(float2*)&C[(rbase + g + 8) * N + col] = make_float2(d[ma][na][2], d[ma][na][3]);
            }
        }
    }
}

// ---------------- conv1d(4, causal) + silu -------------------------------------
__global__ void conv_silu_kernel(const float* __restrict__ conv_w,
                                 const float* __restrict__ conv_b)
{
    int id = blockIdx.x * blockDim.x + threadIdx.x;
    if (id >= L * DI) return;
    int t = id / DI, c = id % DI;
    float acc = conv_b[c];
#pragma unroll
    for (int i = 0; i < 4; i++) {
        int ts = t + i - 3;
        if (ts >= 0)
            acc = fmaf(g_proj[(size_t)ts * NPROJ + OFF_X + c], conv_w[c*4 + i], acc);
    }
    float sig = 1.f / (1.f + expf(-acc));
    g_xconv[id] = acc * sig;
}

// ---------------- dt / Phi / exp tables: block-parallel scan --------------------
// One 256-thread block per head; each thread owns 4 consecutive timesteps.
__global__ __launch_bounds__(256)
void dt_phi_kernel(const float* __restrict__ A_log,
                   const float* __restrict__ dt_bias)
{
    const int h   = blockIdx.x;
    const int tid = threadIdx.x;
    const int lane = tid & 31;
    const int w    = tid >> 5;
    const float Ah   = -expf(A_log[h]);
    const float bias = dt_bias[h];

    __shared__ float wsum[8];

    const int t0 = tid * 4;
    float dt[4];
    float loc = 0.f;
#pragma unroll
    for (int i = 0; i < 4; i++) {
        float xr = g_proj[(size_t)(t0 + i) * NPROJ + OFF_DT + h];
        dt[i] = fmaxf(xr, 0.f) + log1pf(expf(-fabsf(xr))) + bias;
        g_dt[h*L + t0 + i] = dt[i];
        loc += Ah * dt[i];
    }
    // warp inclusive scan of loc
    float s = loc;
#pragma unroll
    for (int o = 1; o < 32; o <<= 1) {
        float v = __shfl_up_sync(0xffffffffu, s, o);
        if (lane >= o) s += v;
    }
    if (lane == 31) wsum[w] = s;
    __syncthreads();
    float wexcl = 0.f;
    if (w > 0) {
#pragma unroll
        for (int i = 0; i < 7; i++)
            if (i < w) wexcl += wsum[i];
    }
    float run = wexcl + (s - loc);     // exclusive prefix for this thread
#pragma unroll
    for (int i = 0; i < 4; i++) {
        run += Ah * dt[i];
        g_eneg[h*L + t0 + i] = expf(fminf(-run, 80.f));
        g_ephi[h*L + t0 + i] = expf(run);
    }
}

// ---------------- SSD stage A ---------------------------------------------------
__global__ __launch_bounds__(256)
void chunk_dstate_kernel()
{
    const int h = blockIdx.x;
    const int c = blockIdx.y;
    const int t0 = c * CT;

    __shared__ float Bsh[CT][DS];
    __shared__ float Xsh[CT][HD];

    const int tid = threadIdx.x;
    for (int idx = tid*4; idx < CT*DS; idx += 256*4) {
        int u = idx / DS, j = idx % DS;
        *(float4*)&Bsh[u][j] =
            *(const float4*)&g_proj[(size_t)(t0+u)*NPROJ + OFF_B + h*DS + j];
    }
    for (int idx = tid*4; idx < CT*HD; idx += 256*4) {
        int u = idx / HD, i = idx % HD;
        float su = g_eneg[h*L + t0 + u] * g_dt[h*L + t0 + u];
        float4 xv = *(const float4*)&g_xconv[(size_t)(t0+u)*DI + h*HD + i];
        xv.x *= su; xv.y *= su; xv.z *= su; xv.w *= su;
        *(float4*)&Xsh[u][i] = xv;
    }
    __syncthreads();

    const int lane = tid & 31;
    const int ty   = tid >> 5;
    const int j0   = ty * 8;
    const int i0   = lane * 4;

    float acc[8][4];
#pragma unroll
    for (int a = 0; a < 8; a++)
#pragma unroll
        for (int b = 0; b < 4; b++) acc[a][b] = 0.f;

    for (int u = 0; u < CT; u++) {
        float4 xv = *(const float4*)&Xsh[u][i0];
#pragma unroll
        for (int a = 0; a < 8; a++) {
            float bj = Bsh[u][j0 + a];
            acc[a][0] = fmaf(bj, xv.x, acc[a][0]);
            acc[a][1] = fmaf(bj, xv.y, acc[a][1]);
            acc[a][2] = fmaf(bj, xv.z, acc[a][2]);
            acc[a][3] = fmaf(bj, xv.w, acc[a][3]);
        }
    }
    float* dst = &g_dS[((size_t)(h*NC + c)) * DS * HD];
#pragma unroll
    for (int a = 0; a < 8; a++)
        *(float4*)&dst[(j0+a)*HD + i0] = *(float4*)&acc[a][0];
}

// ---------------- SSD stage B ---------------------------------------------------
__global__ void state_prefix_kernel()
{
    int g = blockIdx.x * blockDim.x + threadIdx.x;
    if (g >= NH * DS * HD) return;
    int h = g / (DS*HD);
    int e = g % (DS*HD);
    float run = 0.f;
    for (int c = 0; c < NC; c++) {
        size_t idx = ((size_t)(h*NC + c)) * DS * HD + e;
        g_S[idx] = run;
        run += g_dS[idx];
    }
}

// ---------------- SSD stage C ---------------------------------------------------
__global__ __launch_bounds__(256)
void ssd_output_kernel(const float* __restrict__ Dp)
{
    const int h = blockIdx.x;
    const int c = blockIdx.y;
    const int t0 = c * CT;

    __shared__ float Csh [CT][DSP];
    __shared__ float BGsh[CT][DSP];
    __shared__ float sphi[CT], scoef[CT];

    const int tid = threadIdx.x;
    for (int idx = tid*4; idx < CT*DS; idx += 256*4) {
        int u = idx / DS, j = idx % DS;
        size_t row = (size_t)(t0+u) * NPROJ;
        *(float4*)&Csh [u][j] = *(const float4*)&g_proj[row + OFF_C + h*DS + j];
        *(float4*)&BGsh[u][j] = *(const float4*)&g_proj[row + OFF_B + h*DS + j];
    }
    if (tid < CT) {
        sphi [tid] = g_ephi[h*L + t0 + tid];
        scoef[tid] = g_eneg[h*L + t0 + tid] * g_dt[h*L + t0 + tid];
    }
    __syncthreads();

    {
        const int ut = tid & 15;
        const int tt = tid >> 4;
        const int ta = tt * 4;
        const int ua = ut * 4;
        float gacc[4][4];
#pragma unroll
        for (int a = 0; a < 4; a++)
#pragma unroll
            for (int b = 0; b < 4; b++) gacc[a][b] = 0.f;
        for (int k = 0; k < DS; k++) {
            float cr[4], br[4];
#pragma unroll
            for (int a = 0; a < 4; a++) cr[a] = Csh [ta+a][k];
#pragma unroll
            for (int b = 0; b < 4; b++) br[b] = BGsh[ua+b][k];
#pragma unroll
            for (int a = 0; a < 4; a++)
#pragma unroll
                for (int b = 0; b < 4; b++)
                    gacc[a][b] = fmaf(cr[a], br[b], gacc[a][b]);
        }
        __syncthreads();
#pragma unroll
        for (int a = 0; a < 4; a++)
#pragma unroll
            for (int b = 0; b < 4; b++) {
                int t = ta + a, u = ua + b;
                float m = (t >= u) ? sphi[t] * scoef[u] : 0.f;
                BGsh[t][u] = m * gacc[a][b];
            }
        __syncthreads();
    }

    const int lane = tid & 31;
    const int tg   = tid >> 5;
    const int tb   = tg * 8;
    const int i0   = lane * 4;
    const int hbase = h * HD;
    const float dph = Dp[h];
    const float* Srow = &g_S[((size_t)(h*NC + c)) * DS * HD];

    float accI[8][4], accS[8][4];
#pragma unroll
    for (int s = 0; s < 8; s++)
#pragma unroll
        for (int b = 0; b < 4; b++) { accI[s][b] = 0.f; accS[s][b] = 0.f; }

    for (int u = 0; u < CT; u++) {
        float4 xv = *(const float4*)&g_xconv[(size_t)(t0+u)*DI + hbase + i0];
#pragma unroll
        for (int s = 0; s < 8; s++) {
            float gv = BGsh[tb+s][u];
            accI[s][0] = fmaf(gv, xv.x, accI[s][0]);
            accI[s][1] = fmaf(gv, xv.y, accI[s][1]);
            accI[s][2] = fmaf(gv, xv.z, accI[s][2]);
            accI[s][3] = fmaf(gv, xv.w, accI[s][3]);
        }
    }
    for (int j = 0; j < DS; j++) {
        float4 sv = *(const float4*)&Srow[j*HD + i0];
#pragma unroll
        for (int s = 0; s < 8; s++) {
            float cj = Csh[tb+s][j];
            accS[s][0] = fmaf(cj, sv.x, accS[s][0]);
            accS[s][1] = fmaf(cj, sv.y, accS[s][1]);
            accS[s][2] = fmaf(cj, sv.z, accS[s][2]);
            accS[s][3] = fmaf(cj, sv.w, accS[s][3]);
        }
    }
#pragma unroll
    for (int s = 0; s < 8; s++) {
        int t = tb + s;
        float p = sphi[t];
        float4 xv = *(const float4*)&g_xconv[(size_t)(t0+t)*DI + hbase + i0];
        float4 y;
        y.x = fmaf(p, accS[s][0], accI[s][0]) + dph * xv.x;
        y.y = fmaf(p, accS[s][1], accI[s][1]) + dph * xv.y;
        y.z = fmaf(p, accS[s][2], accI[s][2]) + dph * xv.z;
        y.w = fmaf(p, accS[s][3], accI[s][3]) + dph * xv.w;
        *(float4*)&g_yssm[(size_t)(t0+t)*DI + hbase + i0] = y;
    }
}

// ---------------- RMS norm + silu(z) gate + bf16 split (fused) ------------------
__global__ void rms_gate_kernel(const float* __restrict__ norm_w)
{
    const int t = blockIdx.x;
    __shared__ float red[256];
    float s = 0.f;
    for (int c = threadIdx.x; c < DI; c += 256) {
        float v = g_yssm[(size_t)t * DI + c];
        s = fmaf(v, v, s);
    }
    red[threadIdx.x] = s;
    __syncthreads();
    for (int o = 128; o > 0; o >>= 1) {
        if (threadIdx.x < o) red[threadIdx.x] += red[threadIdx.x + o];
        __syncthreads();
    }
    float rms = rsqrtf(red[0] / (float)DI + 1e-5f);
    for (int c = threadIdx.x; c < DI; c += 256) {
        float v = g_yssm[(size_t)t * DI + c];
        float z = g_proj[(size_t)t * NPROJ + c];
        float sig = 1.f / (1.f + expf(-z));
        float yb = v * rms * norm_w[c] * (z * sig);
        __nv_bfloat16 h = __float2bfloat16(yb);
        g_yh[(size_t)t * DI + c] = h;
        g_yl[(size_t)t * DI + c] = __float2bfloat16(yb - __bfloat162float(h));
    }
}

// ---------------- launch --------------------------------------------------------
extern "C" void kernel_launch(void* const* d_in, const int* in_sizes, int n_in,
                              void* d_out, int out_size)
{
    const float* x       = (const float*)d_in[0];
    const float* W_in    = (const float*)d_in[1];
    const float* conv_w  = (const float*)d_in[2];
    const float* conv_b  = (const float*)d_in[3];
    const float* A_log   = (const float*)d_in[4];
    const float* Dp      = (const float*)d_in[5];
    const float* dt_bias = (const float*)d_in[6];
    const float* W_out   = (const float*)d_in[7];
    const float* norm_w  = (const float*)d_in[8];
    float* out = (float*)d_out;

    float *proj_p;
    __nv_bfloat16 *xh, *xl, *w1h, *w1l, *yh, *yl, *w2h, *w2l;
    cudaGetSymbolAddress((void**)&proj_p, g_proj);
    cudaGetSymbolAddress((void**)&xh,  g_xh);  cudaGetSymbolAddress((void**)&xl,  g_xl);
    cudaGetSymbolAddress((void**)&w1h, g_w1h); cudaGetSymbolAddress((void**)&w1l, g_w1l);
    cudaGetSymbolAddress((void**)&yh,  g_yh);  cudaGetSymbolAddress((void**)&yl,  g_yl);
    cudaGetSymbolAddress((void**)&w2h, g_w2h); cudaGetSymbolAddress((void**)&w2l, g_w2l);

    constexpr int SMEM_MA4 = 3 * (2 * 128*GSTRIDE_B + 2 * ARR_B_BYTES);  // 122880
    constexpr int SMEM_MA2 = 3 * (2 *  64*GSTRIDE_B + 2 * ARR_B_BYTES);  //  92160
    cudaFuncSetAttribute(bf16_gemm_nt<4>, cudaFuncAttributeMaxDynamicSharedMemorySize, SMEM_MA4);
    cudaFuncSetAttribute(bf16_gemm_nt<2>, cudaFuncAttributeMaxDynamicSharedMemorySize, SMEM_MA2);

    // 0) bf16 hi/lo splits (input-only, independent)
    split_kernel<<<(L*DM + 255)/256, 256>>>(x, xh, xl, L*DM);
    split_kernel<<<(NPROJ*DM + 255)/256, 256>>>(W_in, w1h, w1l, NPROJ*DM);
    split_kernel<<<(DM*DI + 255)/256, 256>>>(W_out, w2h, w2l, DM*DI);

    // 1) proj = x @ W_in^T  (128-row blocks)
    bf16_gemm_nt<4><<<dim3((NPROJ + 127)/128, L/128), 256, SMEM_MA4>>>(
        L, NPROJ, DM, xh, xl, w1h, w1l, proj_p);

    // 2) causal conv1d + silu
    conv_silu_kernel<<<(L*DI + 255)/256, 256>>>(conv_w, conv_b);

    // 3) dt / Phi (block-parallel scan)
    dt_phi_kernel<<<NH, 256>>>(A_log, dt_bias);

    // 4) SSD pipeline
    chunk_dstate_kernel<<<dim3(NH, NC), 256>>>();
    state_prefix_kernel<<<(NH*DS*HD + 255)/256, 256>>>();
    ssd_output_kernel<<<dim3(NH, NC), 256>>>(Dp);

    // 5) RMS norm + gate + split (fused)
    rms_gate_kernel<<<L, 256>>>(norm_w);

    // 6) out = ybar @ W_out^T  (64-row blocks -> 96 CTAs)
    bf16_gemm_nt<2><<<dim3(DM/128, L/64), 256, SMEM_MA2>>>(
        L, DM, DI, yh, yl, w2h, w2l, out);
}